// round 1
// baseline (speedup 1.0000x reference)
#include <cuda_runtime.h>

// ---------------------------------------------------------------------------
// Attention block: out = softmax((x@qkv_w →q,k,v) qk^T * scale + atts) v @ proj_w + proj_b
// B=8, N=1024, C=1024, H=16, Dh=64.  All fp32.
// Scratch lives in __device__ globals (no allocations anywhere).
// ---------------------------------------------------------------------------

__device__ float g_qkv [8192ull * 3072];   // 96 MB: x @ qkv_w, layout [B*N, 3*C]
__device__ float g_attn[8192ull * 1024];   // 32 MB: attention out, layout [B*N, C] (= [b,n,h*64+d])

// ---------------------------------------------------------------------------
// Tiled fp32 GEMM: C[M,N] = A[M,K] @ B[K,N] (+ bias[N])
// 128x128 block tile, 8x8 per thread (split 4+4), K-tile 32, 256 threads.
// ---------------------------------------------------------------------------
template<bool BIAS>
__global__ __launch_bounds__(256)
void gemm128(const float* __restrict__ A, const float* __restrict__ B,
             const float* __restrict__ bias, float* __restrict__ C,
             int M, int N, int K)
{
    __shared__ float As[32][132];   // A tile transposed: As[k][m], pad 132 (16B-aligned, low STS conflict)
    __shared__ float Bs[32][128];   // B tile natural:    Bs[k][n]

    const int tid = threadIdx.x;
    const int tm  = tid >> 4;        // 0..15 (row group)
    const int tn  = tid & 15;        // 0..15 (col group)
    const int bm  = blockIdx.y << 7;
    const int bn  = blockIdx.x << 7;

    float acc[8][8];
#pragma unroll
    for (int i = 0; i < 8; i++)
#pragma unroll
        for (int j = 0; j < 8; j++) acc[i][j] = 0.f;

    const int arow = tid >> 3;          // 0..31 (tile row per pass)
    const int akc  = (tid & 7) << 2;    // 0..28 (k offset, float4)
    const int bkr  = tid >> 5;          // 0..7  (tile k-row per pass)
    const int bcol = (tid & 31) << 2;   // 0..124

    for (int k0 = 0; k0 < K; k0 += 32) {
        // load A tile (rows bm..bm+127, k0..k0+31), transpose into As[k][m]
#pragma unroll
        for (int p = 0; p < 4; p++) {
            int r = p * 32 + arow;
            float4 v = *reinterpret_cast<const float4*>(&A[(size_t)(bm + r) * K + k0 + akc]);
            As[akc + 0][r] = v.x;
            As[akc + 1][r] = v.y;
            As[akc + 2][r] = v.z;
            As[akc + 3][r] = v.w;
        }
        // load B tile (k0..k0+31, cols bn..bn+127) natural
#pragma unroll
        for (int p = 0; p < 4; p++) {
            int kr = p * 8 + bkr;
            *reinterpret_cast<float4*>(&Bs[kr][bcol]) =
                *reinterpret_cast<const float4*>(&B[(size_t)(k0 + kr) * N + bn + bcol]);
        }
        __syncthreads();

#pragma unroll
        for (int kk = 0; kk < 32; kk++) {
            float a[8], b[8];
            *reinterpret_cast<float4*>(&a[0]) = *reinterpret_cast<float4*>(&As[kk][tm * 4]);
            *reinterpret_cast<float4*>(&a[4]) = *reinterpret_cast<float4*>(&As[kk][64 + tm * 4]);
            *reinterpret_cast<float4*>(&b[0]) = *reinterpret_cast<float4*>(&Bs[kk][tn * 4]);
            *reinterpret_cast<float4*>(&b[4]) = *reinterpret_cast<float4*>(&Bs[kk][64 + tn * 4]);
#pragma unroll
            for (int i = 0; i < 8; i++)
#pragma unroll
                for (int j = 0; j < 8; j++)
                    acc[i][j] = fmaf(a[i], b[j], acc[i][j]);
        }
        __syncthreads();
    }

    float bv[8];
    if (BIAS) {
        *reinterpret_cast<float4*>(&bv[0]) = *reinterpret_cast<const float4*>(&bias[bn + tn * 4]);
        *reinterpret_cast<float4*>(&bv[4]) = *reinterpret_cast<const float4*>(&bias[bn + 64 + tn * 4]);
    }

#pragma unroll
    for (int ih = 0; ih < 2; ih++)
#pragma unroll
        for (int ii = 0; ii < 4; ii++) {
            int row = bm + ih * 64 + tm * 4 + ii;
            int ai  = ih * 4 + ii;
#pragma unroll
            for (int jh = 0; jh < 2; jh++) {
                float4 v;
                v.x = acc[ai][jh * 4 + 0];
                v.y = acc[ai][jh * 4 + 1];
                v.z = acc[ai][jh * 4 + 2];
                v.w = acc[ai][jh * 4 + 3];
                if (BIAS) {
                    v.x += bv[jh * 4 + 0];
                    v.y += bv[jh * 4 + 1];
                    v.z += bv[jh * 4 + 2];
                    v.w += bv[jh * 4 + 3];
                }
                *reinterpret_cast<float4*>(&C[(size_t)row * N + bn + jh * 64 + tn * 4]) = v;
            }
        }
}

// ---------------------------------------------------------------------------
// Flash-style attention, fp32. One block = one (b, h, 64-row Q tile).
// 256 threads as (ty 0..15) x (tx 0..15); thread owns rows ty*4+i, cols tx*4+j
// of each 64x64 tile. Online softmax; additive mask from image_atts.
// Dynamic SMEM 64KB: Qs | Kt(swizzled transpose) | Vs | Ps, each 64x64 fp32.
// Kt swizzle: element (d, r) stored at word d*64 + (((r>>2)^(d>>2))&15)*4 + (r&3)
//   -> transpose STS <=2-way conflict; compute reads (r=4*tx) are conflict-free LDS.128.
// ---------------------------------------------------------------------------
__global__ __launch_bounds__(256)
void attn_kernel(const float* __restrict__ atts, float* __restrict__ out)
{
    extern __shared__ float sm[];
    float* Qs = sm;            // [64][64]
    float* Kt = sm + 4096;     // swizzled [64 d][64 r]
    float* Vs = sm + 8192;     // [64][64]
    float* Ps = sm + 12288;    // [64][64]

    const int tid = threadIdx.x;
    const int ty  = tid >> 4;
    const int tx  = tid & 15;
    const int qt  = blockIdx.x;   // 0..15 q tile
    const int h   = blockIdx.y;   // 0..15 head
    const int b   = blockIdx.z;   // 0..7  batch
    const int N   = 1024, C3 = 3072;
    const float scale = 0.125f;   // Dh^-0.5 = 1/8

    const float* __restrict__ qkv = g_qkv;
    const size_t qkv_base = (size_t)b * N * C3 + h * 64;

    // load Q tile: Qs[r][d]
#pragma unroll
    for (int p = 0; p < 4; p++) {
        int r = p * 16 + ty;
        float4 v = *reinterpret_cast<const float4*>(
            &qkv[qkv_base + (size_t)(qt * 64 + r) * C3 + tx * 4]);
        *reinterpret_cast<float4*>(&Qs[r * 64 + tx * 4]) = v;
    }

    float m[4], l[4], acc[4][4];
#pragma unroll
    for (int i = 0; i < 4; i++) {
        m[i] = -1e30f; l[i] = 0.f;
#pragma unroll
        for (int j = 0; j < 4; j++) acc[i][j] = 0.f;
    }

    for (int kt2 = 0; kt2 < 16; kt2++) {
        __syncthreads();   // previous iter's reads of Kt/Vs/Ps complete
        // load K tile -> swizzled transpose Kt[d][r]; V tile -> Vs[r][d]
#pragma unroll
        for (int p = 0; p < 4; p++) {
            int r = p * 16 + ty;
            size_t g = qkv_base + (size_t)(kt2 * 64 + r) * C3;
            float4 kv = *reinterpret_cast<const float4*>(&qkv[g + 1024 + tx * 4]);
            int cp = ((((r >> 2) ^ tx) & 15) << 2) + (r & 3);
            Kt[(tx * 4 + 0) * 64 + cp] = kv.x;
            Kt[(tx * 4 + 1) * 64 + cp] = kv.y;
            Kt[(tx * 4 + 2) * 64 + cp] = kv.z;
            Kt[(tx * 4 + 3) * 64 + cp] = kv.w;
            float4 vv = *reinterpret_cast<const float4*>(&qkv[g + 2048 + tx * 4]);
            *reinterpret_cast<float4*>(&Vs[r * 64 + tx * 4]) = vv;
        }
        __syncthreads();

        // S = Q @ K^T  (4x4 per thread)
        float s[4][4];
#pragma unroll
        for (int i = 0; i < 4; i++)
#pragma unroll
            for (int j = 0; j < 4; j++) s[i][j] = 0.f;

#pragma unroll
        for (int d4 = 0; d4 < 16; d4++) {
            float q[4][4], kf[4][4];
#pragma unroll
            for (int i = 0; i < 4; i++) {
                float4 t4 = *reinterpret_cast<float4*>(&Qs[(ty * 4 + i) * 64 + d4 * 4]);
                q[i][0] = t4.x; q[i][1] = t4.y; q[i][2] = t4.z; q[i][3] = t4.w;
            }
            int chunk = ((tx ^ d4) & 15) << 2;  // r=4*tx -> r>>2 = tx, r&3 = 0
#pragma unroll
            for (int dd = 0; dd < 4; dd++) {
                float4 t4 = *reinterpret_cast<float4*>(&Kt[(d4 * 4 + dd) * 64 + chunk]);
                kf[dd][0] = t4.x; kf[dd][1] = t4.y; kf[dd][2] = t4.z; kf[dd][3] = t4.w;
            }
#pragma unroll
            for (int i = 0; i < 4; i++)
#pragma unroll
                for (int dd = 0; dd < 4; dd++)
#pragma unroll
                    for (int j = 0; j < 4; j++)
                        s[i][j] = fmaf(q[i][dd], kf[dd][j], s[i][j]);
        }

        // scale + mask + online softmax; write P tile
#pragma unroll
        for (int i = 0; i < 4; i++) {
            int qg = qt * 64 + ty * 4 + i;
            float4 av = *reinterpret_cast<const float4*>(
                &atts[(size_t)b * N * N + (size_t)qg * N + kt2 * 64 + tx * 4]);
            s[i][0] = fmaf(s[i][0], scale, av.x);
            s[i][1] = fmaf(s[i][1], scale, av.y);
            s[i][2] = fmaf(s[i][2], scale, av.z);
            s[i][3] = fmaf(s[i][3], scale, av.w);
            float mt = fmaxf(fmaxf(s[i][0], s[i][1]), fmaxf(s[i][2], s[i][3]));
#pragma unroll
            for (int o = 8; o > 0; o >>= 1)
                mt = fmaxf(mt, __shfl_xor_sync(0xffffffffu, mt, o, 32));
            float mn    = fmaxf(m[i], mt);
            float alpha = __expf(m[i] - mn);
            float p0 = __expf(s[i][0] - mn);
            float p1 = __expf(s[i][1] - mn);
            float p2 = __expf(s[i][2] - mn);
            float p3 = __expf(s[i][3] - mn);
            float rs = (p0 + p1) + (p2 + p3);
#pragma unroll
            for (int o = 8; o > 0; o >>= 1)
                rs += __shfl_xor_sync(0xffffffffu, rs, o, 32);
            l[i] = l[i] * alpha + rs;
            m[i] = mn;
#pragma unroll
            for (int j = 0; j < 4; j++) acc[i][j] *= alpha;
            float4 pv; pv.x = p0; pv.y = p1; pv.z = p2; pv.w = p3;
            *reinterpret_cast<float4*>(&Ps[(ty * 4 + i) * 64 + tx * 4]) = pv;
        }
        __syncthreads();

        // acc += P @ V (same micro-kernel shape as S)
#pragma unroll
        for (int k4 = 0; k4 < 16; k4++) {
            float pf[4][4], vf[4][4];
#pragma unroll
            for (int i = 0; i < 4; i++) {
                float4 t4 = *reinterpret_cast<float4*>(&Ps[(ty * 4 + i) * 64 + k4 * 4]);
                pf[i][0] = t4.x; pf[i][1] = t4.y; pf[i][2] = t4.z; pf[i][3] = t4.w;
            }
#pragma unroll
            for (int kk = 0; kk < 4; kk++) {
                float4 t4 = *reinterpret_cast<float4*>(&Vs[(k4 * 4 + kk) * 64 + tx * 4]);
                vf[kk][0] = t4.x; vf[kk][1] = t4.y; vf[kk][2] = t4.z; vf[kk][3] = t4.w;
            }
#pragma unroll
            for (int i = 0; i < 4; i++)
#pragma unroll
                for (int kk = 0; kk < 4; kk++)
#pragma unroll
                    for (int j = 0; j < 4; j++)
                        acc[i][j] = fmaf(pf[i][kk], vf[kk][j], acc[i][j]);
        }
    }

    // epilogue: normalize and store to [b, n, h*64 + d]
#pragma unroll
    for (int i = 0; i < 4; i++) {
        float inv = 1.f / l[i];
        int qg = qt * 64 + ty * 4 + i;
        float4 v;
        v.x = acc[i][0] * inv; v.y = acc[i][1] * inv;
        v.z = acc[i][2] * inv; v.w = acc[i][3] * inv;
        *reinterpret_cast<float4*>(&out[(size_t)(b * N + qg) * 1024 + h * 64 + tx * 4]) = v;
    }
}

// ---------------------------------------------------------------------------
// Launch: qkv GEMM -> flash attention -> projection GEMM (+bias)
// inputs (metadata order): 0 x, 1 text_embeds(unused), 2 image_atts,
//                          3 qkv_w, 4 proj_w, 5 proj_b
// ---------------------------------------------------------------------------
extern "C" void kernel_launch(void* const* d_in, const int* in_sizes, int n_in,
                              void* d_out, int out_size)
{
    (void)in_sizes; (void)n_in; (void)out_size;
    const float* x      = (const float*)d_in[0];
    const float* atts   = (const float*)d_in[2];
    const float* qkv_w  = (const float*)d_in[3];
    const float* proj_w = (const float*)d_in[4];
    const float* proj_b = (const float*)d_in[5];
    float* out = (float*)d_out;

    float *qkv_buf, *attn_buf;
    cudaGetSymbolAddress((void**)&qkv_buf,  g_qkv);
    cudaGetSymbolAddress((void**)&attn_buf, g_attn);

    cudaFuncSetAttribute(attn_kernel, cudaFuncAttributeMaxDynamicSharedMemorySize, 65536);

    // 1) qkv = x @ qkv_w : [8192,1024] @ [1024,3072]
    gemm128<false><<<dim3(3072 / 128, 8192 / 128), 256>>>(x, qkv_w, nullptr, qkv_buf,
                                                          8192, 3072, 1024);
    // 2) attention -> g_attn  (grid: 16 q-tiles x 16 heads x 8 batch)
    attn_kernel<<<dim3(16, 16, 8), 256, 65536>>>(atts, attn_buf);
    // 3) out = attn @ proj_w + proj_b : [8192,1024] @ [1024,1024]
    gemm128<true><<<dim3(1024 / 128, 8192 / 128), 256>>>(attn_buf, proj_w, proj_b, out,
                                                         8192, 1024, 1024);
}

// round 6
// speedup vs baseline: 1.5691x; 1.5691x over previous
#include <cuda_runtime.h>
#include <cuda_bf16.h>
#include <cstdint>

// ===========================================================================
// Attention block on GB300 (ptxas target sm_103: NO tcgen05 — use portable
// mma.sync bf16 HMMA path). GEMMs: bf16 3-term fp32 emulation (hh+hl+lh).
// Attention: SIMT fp32 (unchanged, passing).
// ===========================================================================

// ---- scratch (device globals; no allocations allowed) ---------------------
__device__ float         g_qkv [8192ull * 3072];
__device__ float         g_attn[8192ull * 1024];
__device__ __nv_bfloat16 g_xhi [8192ull * 1024];
__device__ __nv_bfloat16 g_xlo [8192ull * 1024];
__device__ __nv_bfloat16 g_w1hi[3072ull * 1024];   // qkv_w^T split, [N,K]
__device__ __nv_bfloat16 g_w1lo[3072ull * 1024];
__device__ __nv_bfloat16 g_ahi [8192ull * 1024];
__device__ __nv_bfloat16 g_alo [8192ull * 1024];
__device__ __nv_bfloat16 g_w2hi[1024ull * 1024];   // proj_w^T split, [N,K]
__device__ __nv_bfloat16 g_w2lo[1024ull * 1024];

// ---- ptx helpers ----------------------------------------------------------
__device__ __forceinline__ uint32_t smem_u32(const void* p) {
    uint32_t a;
    asm("{ .reg .u64 t; cvta.to.shared.u64 t, %1; cvt.u32.u64 %0, t; }"
        : "=r"(a) : "l"(p));
    return a;
}

__device__ __forceinline__ void cp16(uint32_t saddr, const void* g) {
    asm volatile("cp.async.cg.shared.global [%0], [%1], 16;"
                 :: "r"(saddr), "l"(g));
}
#define CP_COMMIT() asm volatile("cp.async.commit_group;" ::: "memory")
#define CP_WAIT(n)  asm volatile("cp.async.wait_group %0;" :: "n"(n) : "memory")

__device__ __forceinline__ void ldsm4(uint32_t* r, uint32_t addr) {
    asm volatile("ldmatrix.sync.aligned.m8n8.x4.shared.b16 {%0,%1,%2,%3}, [%4];"
                 : "=r"(r[0]), "=r"(r[1]), "=r"(r[2]), "=r"(r[3]) : "r"(addr));
}

__device__ __forceinline__ void mma_bf16(float* d, const uint32_t* a, const uint32_t* b) {
    asm volatile("mma.sync.aligned.m16n8k16.row.col.f32.bf16.bf16.f32 "
                 "{%0,%1,%2,%3}, {%4,%5,%6,%7}, {%8,%9}, {%0,%1,%2,%3};"
                 : "+f"(d[0]), "+f"(d[1]), "+f"(d[2]), "+f"(d[3])
                 : "r"(a[0]), "r"(a[1]), "r"(a[2]), "r"(a[3]),
                   "r"(b[0]), "r"(b[1]));
}

// ---------------------------------------------------------------------------
// fp32 -> bf16 hi/lo split (elementwise, vectorized x4)
// ---------------------------------------------------------------------------
__global__ __launch_bounds__(256)
void split_kernel(const float* __restrict__ in, __nv_bfloat16* __restrict__ hi,
                  __nv_bfloat16* __restrict__ lo, int n4)
{
    int i = blockIdx.x * 256 + threadIdx.x;
    if (i >= n4) return;
    float4 v = reinterpret_cast<const float4*>(in)[i];
    __nv_bfloat16 h[4], l[4];
    float f[4] = {v.x, v.y, v.z, v.w};
#pragma unroll
    for (int j = 0; j < 4; j++) {
        h[j] = __float2bfloat16(f[j]);
        l[j] = __float2bfloat16(f[j] - __bfloat162float(h[j]));
    }
    reinterpret_cast<uint2*>(hi)[i] = *reinterpret_cast<uint2*>(h);
    reinterpret_cast<uint2*>(lo)[i] = *reinterpret_cast<uint2*>(l);
}

// ---------------------------------------------------------------------------
// W[K,N] fp32 -> W^T[N,K] bf16 hi/lo  (tiled transpose + split)
// ---------------------------------------------------------------------------
__global__ __launch_bounds__(256)
void tsplit_kernel(const float* __restrict__ W, __nv_bfloat16* __restrict__ hi,
                   __nv_bfloat16* __restrict__ lo, int K, int N)
{
    __shared__ float tile[32][33];
    int tx = threadIdx.x, ty = threadIdx.y;
    int bn = blockIdx.x * 32, bk = blockIdx.y * 32;
#pragma unroll
    for (int r = 0; r < 4; r++)
        tile[ty + r * 8][tx] = W[(size_t)(bk + ty + r * 8) * N + bn + tx];
    __syncthreads();
#pragma unroll
    for (int r = 0; r < 4; r++) {
        int n = bn + ty + r * 8;
        int k = bk + tx;
        float a = tile[tx][ty + r * 8];
        __nv_bfloat16 h = __float2bfloat16(a);
        hi[(size_t)n * K + k] = h;
        lo[(size_t)n * K + k] = __float2bfloat16(a - __bfloat162float(h));
    }
}

// ---------------------------------------------------------------------------
// HMMA GEMM: C[M,N] = (Ahi+Alo)[M,K] @ (Bhi+Blo)^T  (+ bias)
// A,B bf16 hi/lo, [rows,K] K-major. CTA 128x128, 8 warps (32m x 64n each).
// K-chunk 32, double-buffered cp.async pipeline.
// SMEM tile rows padded to 80B => conflict-free ldmatrix (5m mod 8 full-phase).
// Stage layout (bytes): Ahi[128*80] | Alo | Bhi | Blo  = 40960 B; 2 stages.
// ---------------------------------------------------------------------------
template<bool BIAS>
__global__ __launch_bounds__(256)
void gemm_mma(const __nv_bfloat16* __restrict__ Ahi, const __nv_bfloat16* __restrict__ Alo,
              const __nv_bfloat16* __restrict__ Bhi, const __nv_bfloat16* __restrict__ Blo,
              const float* __restrict__ bias, float* __restrict__ C,
              int M, int N, int K)
{
    extern __shared__ char smem[];
    const uint32_t sbase = smem_u32(smem);
    const int STAGE = 40960, TILE = 10240;

    const int tid  = threadIdx.x;
    const int warp = tid >> 5;
    const int lane = tid & 31;
    const int bm = blockIdx.y << 7;
    const int bn = blockIdx.x << 7;

    const int wm = (warp & 3) * 32;   // warp m offset (local)
    const int wn = (warp >> 2) * 64;  // warp n offset (local)

    // ldmatrix lane addressing (tile-local)
    const int aRow = wm + (lane & 7) + ((lane & 8) ? 8 : 0);
    const int aKb  = (lane & 16) ? 16 : 0;
    const int bRow = (lane & 7) + ((lane & 16) ? 8 : 0);
    const int bKb  = (lane & 8) ? 16 : 0;

    // global load mapping: per tile, 2 x 16B per thread
    const int r0 = tid >> 2, c0 = (tid & 3);          // idx = tid
    const int r1 = (tid + 256) >> 2, c1 = (tid & 3);  // idx = tid+256 (c same)

    float acc[2][8][4];
#pragma unroll
    for (int mi = 0; mi < 2; mi++)
#pragma unroll
        for (int nj = 0; nj < 8; nj++)
#pragma unroll
            for (int e = 0; e < 4; e++) acc[mi][nj][e] = 0.f;

    const int nk = K >> 5;

    // ---- stage loader ----
    auto load_stage = [&](int s, int k0) {
        uint32_t sa = sbase + s * STAGE;
        // A hi
        cp16(sa + r0 * 80 + c0 * 16, Ahi + (size_t)(bm + r0) * K + k0 + c0 * 8);
        cp16(sa + r1 * 80 + c1 * 16, Ahi + (size_t)(bm + r1) * K + k0 + c1 * 8);
        // A lo
        cp16(sa + TILE + r0 * 80 + c0 * 16, Alo + (size_t)(bm + r0) * K + k0 + c0 * 8);
        cp16(sa + TILE + r1 * 80 + c1 * 16, Alo + (size_t)(bm + r1) * K + k0 + c1 * 8);
        // B hi
        cp16(sa + 2 * TILE + r0 * 80 + c0 * 16, Bhi + (size_t)(bn + r0) * K + k0 + c0 * 8);
        cp16(sa + 2 * TILE + r1 * 80 + c1 * 16, Bhi + (size_t)(bn + r1) * K + k0 + c1 * 8);
        // B lo
        cp16(sa + 3 * TILE + r0 * 80 + c0 * 16, Blo + (size_t)(bn + r0) * K + k0 + c0 * 8);
        cp16(sa + 3 * TILE + r1 * 80 + c1 * 16, Blo + (size_t)(bn + r1) * K + k0 + c1 * 8);
        CP_COMMIT();
    };

    load_stage(0, 0);

    for (int ch = 0; ch < nk; ch++) {
        const uint32_t sa = sbase + (ch & 1) * STAGE;
        if (ch + 1 < nk) { load_stage((ch + 1) & 1, (ch + 1) << 5); CP_WAIT(1); }
        else             { CP_WAIT(0); }
        __syncthreads();

#pragma unroll
        for (int ks = 0; ks < 2; ks++) {
            uint32_t Ah[2][4], Al[2][4], Bh[8][2], Bl[8][2];
#pragma unroll
            for (int mi = 0; mi < 2; mi++) {
                uint32_t ra = (uint32_t)((aRow + mi * 16) * 80 + ks * 32 + aKb);
                ldsm4(Ah[mi], sa + ra);
                ldsm4(Al[mi], sa + TILE + ra);
            }
#pragma unroll
            for (int p = 0; p < 4; p++) {
                uint32_t rb = (uint32_t)((wn + p * 16 + bRow) * 80 + ks * 32 + bKb);
                ldsm4(&Bh[p * 2][0], sa + 2 * TILE + rb);
                ldsm4(&Bl[p * 2][0], sa + 3 * TILE + rb);
            }
#pragma unroll
            for (int mi = 0; mi < 2; mi++)
#pragma unroll
                for (int nj = 0; nj < 8; nj++)
                    mma_bf16(acc[mi][nj], Ah[mi], Bh[nj]);
#pragma unroll
            for (int mi = 0; mi < 2; mi++)
#pragma unroll
                for (int nj = 0; nj < 8; nj++)
                    mma_bf16(acc[mi][nj], Ah[mi], Bl[nj]);
#pragma unroll
            for (int mi = 0; mi < 2; mi++)
#pragma unroll
                for (int nj = 0; nj < 8; nj++)
                    mma_bf16(acc[mi][nj], Al[mi], Bh[nj]);
        }
        __syncthreads();
    }

    // ---- epilogue: fragment -> global ----
    const int orow = bm + wm + (lane >> 2);
    const int ocol = bn + wn + (lane & 3) * 2;
#pragma unroll
    for (int mi = 0; mi < 2; mi++) {
        const int rA = orow + mi * 16;
#pragma unroll
        for (int nj = 0; nj < 8; nj++) {
            const int c = ocol + nj * 8;
            float b0 = 0.f, b1 = 0.f;
            if (BIAS) { b0 = bias[c]; b1 = bias[c + 1]; }
            float2 v0, v1;
            v0.x = acc[mi][nj][0] + b0; v0.y = acc[mi][nj][1] + b1;
            v1.x = acc[mi][nj][2] + b0; v1.y = acc[mi][nj][3] + b1;
            *reinterpret_cast<float2*>(&C[(size_t)rA * N + c])       = v0;
            *reinterpret_cast<float2*>(&C[(size_t)(rA + 8) * N + c]) = v1;
        }
    }
}

// ---------------------------------------------------------------------------
// Flash-style attention, fp32 SIMT (unchanged from round 1, passing).
// ---------------------------------------------------------------------------
__global__ __launch_bounds__(256)
void attn_kernel(const float* __restrict__ atts, float* __restrict__ out)
{
    extern __shared__ float sm[];
    float* Qs = sm;
    float* Kt = sm + 4096;
    float* Vs = sm + 8192;
    float* Ps = sm + 12288;

    const int tid = threadIdx.x;
    const int ty  = tid >> 4;
    const int tx  = tid & 15;
    const int qt  = blockIdx.x;
    const int h   = blockIdx.y;
    const int b   = blockIdx.z;
    const int N   = 1024, C3 = 3072;
    const float scale = 0.125f;

    const float* __restrict__ qkv = g_qkv;
    const size_t qkv_base = (size_t)b * N * C3 + h * 64;

#pragma unroll
    for (int p = 0; p < 4; p++) {
        int r = p * 16 + ty;
        float4 v = *reinterpret_cast<const float4*>(
            &qkv[qkv_base + (size_t)(qt * 64 + r) * C3 + tx * 4]);
        *reinterpret_cast<float4*>(&Qs[r * 64 + tx * 4]) = v;
    }

    float m[4], l[4], acc[4][4];
#pragma unroll
    for (int i = 0; i < 4; i++) {
        m[i] = -1e30f; l[i] = 0.f;
#pragma unroll
        for (int j = 0; j < 4; j++) acc[i][j] = 0.f;
    }

    for (int kt2 = 0; kt2 < 16; kt2++) {
        __syncthreads();
#pragma unroll
        for (int p = 0; p < 4; p++) {
            int r = p * 16 + ty;
            size_t g = qkv_base + (size_t)(kt2 * 64 + r) * C3;
            float4 kv = *reinterpret_cast<const float4*>(&qkv[g + 1024 + tx * 4]);
            int cp = ((((r >> 2) ^ tx) & 15) << 2) + (r & 3);
            Kt[(tx * 4 + 0) * 64 + cp] = kv.x;
            Kt[(tx * 4 + 1) * 64 + cp] = kv.y;
            Kt[(tx * 4 + 2) * 64 + cp] = kv.z;
            Kt[(tx * 4 + 3) * 64 + cp] = kv.w;
            float4 vv = *reinterpret_cast<const float4*>(&qkv[g + 2048 + tx * 4]);
            *reinterpret_cast<float4*>(&Vs[r * 64 + tx * 4]) = vv;
        }
        __syncthreads();

        float s[4][4];
#pragma unroll
        for (int i = 0; i < 4; i++)
#pragma unroll
            for (int j = 0; j < 4; j++) s[i][j] = 0.f;

#pragma unroll
        for (int d4 = 0; d4 < 16; d4++) {
            float q[4][4], kf[4][4];
#pragma unroll
            for (int i = 0; i < 4; i++) {
                float4 t4 = *reinterpret_cast<float4*>(&Qs[(ty * 4 + i) * 64 + d4 * 4]);
                q[i][0] = t4.x; q[i][1] = t4.y; q[i][2] = t4.z; q[i][3] = t4.w;
            }
            int chunk = ((tx ^ d4) & 15) << 2;
#pragma unroll
            for (int dd = 0; dd < 4; dd++) {
                float4 t4 = *reinterpret_cast<float4*>(&Kt[(d4 * 4 + dd) * 64 + chunk]);
                kf[dd][0] = t4.x; kf[dd][1] = t4.y; kf[dd][2] = t4.z; kf[dd][3] = t4.w;
            }
#pragma unroll
            for (int i = 0; i < 4; i++)
#pragma unroll
                for (int dd = 0; dd < 4; dd++)
#pragma unroll
                    for (int j = 0; j < 4; j++)
                        s[i][j] = fmaf(q[i][dd], kf[dd][j], s[i][j]);
        }

#pragma unroll
        for (int i = 0; i < 4; i++) {
            int qg = qt * 64 + ty * 4 + i;
            float4 av = *reinterpret_cast<const float4*>(
                &atts[(size_t)b * N * N + (size_t)qg * N + kt2 * 64 + tx * 4]);
            s[i][0] = fmaf(s[i][0], scale, av.x);
            s[i][1] = fmaf(s[i][1], scale, av.y);
            s[i][2] = fmaf(s[i][2], scale, av.z);
            s[i][3] = fmaf(s[i][3], scale, av.w);
            float mt = fmaxf(fmaxf(s[i][0], s[i][1]), fmaxf(s[i][2], s[i][3]));
#pragma unroll
            for (int o = 8; o > 0; o >>= 1)
                mt = fmaxf(mt, __shfl_xor_sync(0xffffffffu, mt, o, 32));
            float mn    = fmaxf(m[i], mt);
            float alpha = __expf(m[i] - mn);
            float p0 = __expf(s[i][0] - mn);
            float p1 = __expf(s[i][1] - mn);
            float p2 = __expf(s[i][2] - mn);
            float p3 = __expf(s[i][3] - mn);
            float rs = (p0 + p1) + (p2 + p3);
#pragma unroll
            for (int o = 8; o > 0; o >>= 1)
                rs += __shfl_xor_sync(0xffffffffu, rs, o, 32);
            l[i] = l[i] * alpha + rs;
            m[i] = mn;
#pragma unroll
            for (int j = 0; j < 4; j++) acc[i][j] *= alpha;
            float4 pv; pv.x = p0; pv.y = p1; pv.z = p2; pv.w = p3;
            *reinterpret_cast<float4*>(&Ps[(ty * 4 + i) * 64 + tx * 4]) = pv;
        }
        __syncthreads();

#pragma unroll
        for (int k4 = 0; k4 < 16; k4++) {
            float pf[4][4], vf[4][4];
#pragma unroll
            for (int i = 0; i < 4; i++) {
                float4 t4 = *reinterpret_cast<float4*>(&Ps[(ty * 4 + i) * 64 + k4 * 4]);
                pf[i][0] = t4.x; pf[i][1] = t4.y; pf[i][2] = t4.z; pf[i][3] = t4.w;
            }
#pragma unroll
            for (int kk = 0; kk < 4; kk++) {
                float4 t4 = *reinterpret_cast<float4*>(&Vs[(k4 * 4 + kk) * 64 + tx * 4]);
                vf[kk][0] = t4.x; vf[kk][1] = t4.y; vf[kk][2] = t4.z; vf[kk][3] = t4.w;
            }
#pragma unroll
            for (int i = 0; i < 4; i++)
#pragma unroll
                for (int kk = 0; kk < 4; kk++)
#pragma unroll
                    for (int j = 0; j < 4; j++)
                        acc[i][j] = fmaf(pf[i][kk], vf[kk][j], acc[i][j]);
        }
    }

#pragma unroll
    for (int i = 0; i < 4; i++) {
        float inv = 1.f / l[i];
        int qg = qt * 64 + ty * 4 + i;
        float4 v;
        v.x = acc[i][0] * inv; v.y = acc[i][1] * inv;
        v.z = acc[i][2] * inv; v.w = acc[i][3] * inv;
        *reinterpret_cast<float4*>(&out[(size_t)(b * N + qg) * 1024 + h * 64 + tx * 4]) = v;
    }
}

// ---------------------------------------------------------------------------
// Launch sequence
// inputs: 0 x, 1 text_embeds(unused), 2 image_atts, 3 qkv_w, 4 proj_w, 5 proj_b
// ---------------------------------------------------------------------------
extern "C" void kernel_launch(void* const* d_in, const int* in_sizes, int n_in,
                              void* d_out, int out_size)
{
    (void)in_sizes; (void)n_in; (void)out_size;
    const float* x      = (const float*)d_in[0];
    const float* atts   = (const float*)d_in[2];
    const float* qkv_w  = (const float*)d_in[3];
    const float* proj_w = (const float*)d_in[4];
    const float* proj_b = (const float*)d_in[5];
    float* out = (float*)d_out;

    float *qkv_buf, *attn_buf;
    __nv_bfloat16 *xhi, *xlo, *w1hi, *w1lo, *ahi, *alo, *w2hi, *w2lo;
    cudaGetSymbolAddress((void**)&qkv_buf,  g_qkv);
    cudaGetSymbolAddress((void**)&attn_buf, g_attn);
    cudaGetSymbolAddress((void**)&xhi,  g_xhi);
    cudaGetSymbolAddress((void**)&xlo,  g_xlo);
    cudaGetSymbolAddress((void**)&w1hi, g_w1hi);
    cudaGetSymbolAddress((void**)&w1lo, g_w1lo);
    cudaGetSymbolAddress((void**)&ahi,  g_ahi);
    cudaGetSymbolAddress((void**)&alo,  g_alo);
    cudaGetSymbolAddress((void**)&w2hi, g_w2hi);
    cudaGetSymbolAddress((void**)&w2lo, g_w2lo);

    cudaFuncSetAttribute(attn_kernel, cudaFuncAttributeMaxDynamicSharedMemorySize, 65536);
    cudaFuncSetAttribute(gemm_mma<false>, cudaFuncAttributeMaxDynamicSharedMemorySize, 81920);
    cudaFuncSetAttribute(gemm_mma<true>,  cudaFuncAttributeMaxDynamicSharedMemorySize, 81920);

    // 1) split x -> bf16 hi/lo; transpose+split qkv_w
    split_kernel<<<8192, 256>>>(x, xhi, xlo, 8192 * 1024 / 4);
    tsplit_kernel<<<dim3(96, 32), dim3(32, 8)>>>(qkv_w, w1hi, w1lo, 1024, 3072);

    // 2) qkv = x @ qkv_w  (HMMA, 3-term)
    gemm_mma<false><<<dim3(24, 64), 256, 81920>>>(xhi, xlo, w1hi, w1lo, nullptr,
                                                  qkv_buf, 8192, 3072, 1024);

    // 3) flash attention (fp32 SIMT)
    attn_kernel<<<dim3(16, 16, 8), 256, 65536>>>(atts, attn_buf);

    // 4) split attention out; transpose+split proj_w
    split_kernel<<<8192, 256>>>(attn_buf, ahi, alo, 8192 * 1024 / 4);
    tsplit_kernel<<<dim3(32, 32), dim3(32, 8)>>>(proj_w, w2hi, w2lo, 1024, 1024);

    // 5) out = attn @ proj_w + proj_b  (HMMA, 3-term)
    gemm_mma<true><<<dim3(8, 64), 256, 81920>>>(ahi, alo, w2hi, w2lo, proj_b,
                                                out, 8192, 1024, 1024);
}

// round 9
// speedup vs baseline: 2.2587x; 1.4395x over previous
#include <cuda_runtime.h>
#include <cuda_bf16.h>
#include <cstdint>

// ===========================================================================
// Attention block, GB300 (sm_103 ptxas target -> portable mma.sync HMMA).
// Round 9 (= round-7 resubmit; repeated infra timeouts): attention tensorized
// (bf16 3-term emulation for S=QK^T and P*V), GEMM1 writes bf16 hi/lo
// directly, attention writes bf16 hi/lo directly.
// ===========================================================================

// ---- scratch (device globals; no allocations allowed) ---------------------
__device__ __nv_bfloat16 g_qkvhi[8192ull * 3072];  // gemm1 out hi
__device__ __nv_bfloat16 g_qkvlo[8192ull * 3072];  // gemm1 out lo
__device__ __nv_bfloat16 g_xhi [8192ull * 1024];
__device__ __nv_bfloat16 g_xlo [8192ull * 1024];
__device__ __nv_bfloat16 g_w1hi[3072ull * 1024];   // qkv_w^T split, [N,K]
__device__ __nv_bfloat16 g_w1lo[3072ull * 1024];
__device__ __nv_bfloat16 g_ahi [8192ull * 1024];   // attention out hi
__device__ __nv_bfloat16 g_alo [8192ull * 1024];   // attention out lo
__device__ __nv_bfloat16 g_w2hi[1024ull * 1024];   // proj_w^T split, [N,K]
__device__ __nv_bfloat16 g_w2lo[1024ull * 1024];

// ---- ptx helpers ----------------------------------------------------------
__device__ __forceinline__ uint32_t smem_u32(const void* p) {
    uint32_t a;
    asm("{ .reg .u64 t; cvta.to.shared.u64 t, %1; cvt.u32.u64 %0, t; }"
        : "=r"(a) : "l"(p));
    return a;
}

__device__ __forceinline__ void cp16(uint32_t saddr, const void* g) {
    asm volatile("cp.async.cg.shared.global [%0], [%1], 16;"
                 :: "r"(saddr), "l"(g));
}
#define CP_COMMIT() asm volatile("cp.async.commit_group;" ::: "memory")
#define CP_WAIT(n)  asm volatile("cp.async.wait_group %0;" :: "n"(n) : "memory")

__device__ __forceinline__ void ldsm4(uint32_t* r, uint32_t addr) {
    asm volatile("ldmatrix.sync.aligned.m8n8.x4.shared.b16 {%0,%1,%2,%3}, [%4];"
                 : "=r"(r[0]), "=r"(r[1]), "=r"(r[2]), "=r"(r[3]) : "r"(addr));
}
__device__ __forceinline__ void ldsm4t(uint32_t* r, uint32_t addr) {
    asm volatile("ldmatrix.sync.aligned.m8n8.x4.trans.shared.b16 {%0,%1,%2,%3}, [%4];"
                 : "=r"(r[0]), "=r"(r[1]), "=r"(r[2]), "=r"(r[3]) : "r"(addr));
}

__device__ __forceinline__ void mma_bf16(float* d, const uint32_t* a, const uint32_t* b) {
    asm volatile("mma.sync.aligned.m16n8k16.row.col.f32.bf16.bf16.f32 "
                 "{%0,%1,%2,%3}, {%4,%5,%6,%7}, {%8,%9}, {%0,%1,%2,%3};"
                 : "+f"(d[0]), "+f"(d[1]), "+f"(d[2]), "+f"(d[3])
                 : "r"(a[0]), "r"(a[1]), "r"(a[2]), "r"(a[3]),
                   "r"(b[0]), "r"(b[1]));
}

// pack two fp32 -> bf16x2 hi + bf16x2 residual lo (e0 in low halves)
__device__ __forceinline__ void packsplit(uint32_t& hi, uint32_t& lo, float e0, float e1) {
    uint32_t h;
    asm("cvt.rn.bf16x2.f32 %0, %1, %2;" : "=r"(h) : "f"(e1), "f"(e0));
    float f0 = __uint_as_float(h << 16);
    float f1 = __uint_as_float(h & 0xffff0000u);
    uint32_t l;
    asm("cvt.rn.bf16x2.f32 %0, %1, %2;" : "=r"(l) : "f"(e1 - f1), "f"(e0 - f0));
    hi = h; lo = l;
}

// ---------------------------------------------------------------------------
// fp32 -> bf16 hi/lo split (elementwise, vectorized x4)
// ---------------------------------------------------------------------------
__global__ __launch_bounds__(256)
void split_kernel(const float* __restrict__ in, __nv_bfloat16* __restrict__ hi,
                  __nv_bfloat16* __restrict__ lo, int n4)
{
    int i = blockIdx.x * 256 + threadIdx.x;
    if (i >= n4) return;
    float4 v = reinterpret_cast<const float4*>(in)[i];
    __nv_bfloat16 h[4], l[4];
    float f[4] = {v.x, v.y, v.z, v.w};
#pragma unroll
    for (int j = 0; j < 4; j++) {
        h[j] = __float2bfloat16(f[j]);
        l[j] = __float2bfloat16(f[j] - __bfloat162float(h[j]));
    }
    reinterpret_cast<uint2*>(hi)[i] = *reinterpret_cast<uint2*>(h);
    reinterpret_cast<uint2*>(lo)[i] = *reinterpret_cast<uint2*>(l);
}

// ---------------------------------------------------------------------------
// W[K,N] fp32 -> W^T[N,K] bf16 hi/lo  (tiled transpose + split)
// ---------------------------------------------------------------------------
__global__ __launch_bounds__(256)
void tsplit_kernel(const float* __restrict__ W, __nv_bfloat16* __restrict__ hi,
                   __nv_bfloat16* __restrict__ lo, int K, int N)
{
    __shared__ float tile[32][33];
    int tx = threadIdx.x, ty = threadIdx.y;
    int bn = blockIdx.x * 32, bk = blockIdx.y * 32;
#pragma unroll
    for (int r = 0; r < 4; r++)
        tile[ty + r * 8][tx] = W[(size_t)(bk + ty + r * 8) * N + bn + tx];
    __syncthreads();
#pragma unroll
    for (int r = 0; r < 4; r++) {
        int n = bn + ty + r * 8;
        int k = bk + tx;
        float a = tile[tx][ty + r * 8];
        __nv_bfloat16 h = __float2bfloat16(a);
        hi[(size_t)n * K + k] = h;
        lo[(size_t)n * K + k] = __float2bfloat16(a - __bfloat162float(h));
    }
}

// ---------------------------------------------------------------------------
// HMMA GEMM: C = (Ahi+Alo) @ (Bhi+Blo)^T (+bias). 128x128 CTA, 8 warps,
// K-chunk 32, double-buffered cp.async, 80B-pitch SMEM (conflict-free ldsm).
// SPLIT=true: write bf16 hi/lo (Chi/Clo) instead of fp32 C.
// ---------------------------------------------------------------------------
template<bool BIAS, bool SPLIT>
__global__ __launch_bounds__(256)
void gemm_mma(const __nv_bfloat16* __restrict__ Ahi, const __nv_bfloat16* __restrict__ Alo,
              const __nv_bfloat16* __restrict__ Bhi, const __nv_bfloat16* __restrict__ Blo,
              const float* __restrict__ bias, float* __restrict__ C,
              __nv_bfloat16* __restrict__ Chi, __nv_bfloat16* __restrict__ Clo,
              int M, int N, int K)
{
    extern __shared__ char smem[];
    const uint32_t sbase = smem_u32(smem);
    const int STAGE = 40960, TILE = 10240;

    const int tid  = threadIdx.x;
    const int warp = tid >> 5;
    const int lane = tid & 31;
    const int bm = blockIdx.y << 7;
    const int bn = blockIdx.x << 7;

    const int wm = (warp & 3) * 32;
    const int wn = (warp >> 2) * 64;

    const int aRow = wm + (lane & 7) + ((lane & 8) ? 8 : 0);
    const int aKb  = (lane & 16) ? 16 : 0;
    const int bRow = (lane & 7) + ((lane & 16) ? 8 : 0);
    const int bKb  = (lane & 8) ? 16 : 0;

    const int r0 = tid >> 2, c0 = (tid & 3);
    const int r1 = (tid + 256) >> 2, c1 = (tid & 3);

    float acc[2][8][4];
#pragma unroll
    for (int mi = 0; mi < 2; mi++)
#pragma unroll
        for (int nj = 0; nj < 8; nj++)
#pragma unroll
            for (int e = 0; e < 4; e++) acc[mi][nj][e] = 0.f;

    const int nk = K >> 5;

    auto load_stage = [&](int s, int k0) {
        uint32_t sa = sbase + s * STAGE;
        cp16(sa + r0 * 80 + c0 * 16, Ahi + (size_t)(bm + r0) * K + k0 + c0 * 8);
        cp16(sa + r1 * 80 + c1 * 16, Ahi + (size_t)(bm + r1) * K + k0 + c1 * 8);
        cp16(sa + TILE + r0 * 80 + c0 * 16, Alo + (size_t)(bm + r0) * K + k0 + c0 * 8);
        cp16(sa + TILE + r1 * 80 + c1 * 16, Alo + (size_t)(bm + r1) * K + k0 + c1 * 8);
        cp16(sa + 2 * TILE + r0 * 80 + c0 * 16, Bhi + (size_t)(bn + r0) * K + k0 + c0 * 8);
        cp16(sa + 2 * TILE + r1 * 80 + c1 * 16, Bhi + (size_t)(bn + r1) * K + k0 + c1 * 8);
        cp16(sa + 3 * TILE + r0 * 80 + c0 * 16, Blo + (size_t)(bn + r0) * K + k0 + c0 * 8);
        cp16(sa + 3 * TILE + r1 * 80 + c1 * 16, Blo + (size_t)(bn + r1) * K + k0 + c1 * 8);
        CP_COMMIT();
    };

    load_stage(0, 0);

    for (int ch = 0; ch < nk; ch++) {
        const uint32_t sa = sbase + (ch & 1) * STAGE;
        if (ch + 1 < nk) { load_stage((ch + 1) & 1, (ch + 1) << 5); CP_WAIT(1); }
        else             { CP_WAIT(0); }
        __syncthreads();

#pragma unroll
        for (int ks = 0; ks < 2; ks++) {
            uint32_t Ah[2][4], Al[2][4], Bh[8][2], Bl[8][2];
#pragma unroll
            for (int mi = 0; mi < 2; mi++) {
                uint32_t ra = (uint32_t)((aRow + mi * 16) * 80 + ks * 32 + aKb);
                ldsm4(Ah[mi], sa + ra);
                ldsm4(Al[mi], sa + TILE + ra);
            }
#pragma unroll
            for (int p = 0; p < 4; p++) {
                uint32_t rb = (uint32_t)((wn + p * 16 + bRow) * 80 + ks * 32 + bKb);
                ldsm4(&Bh[p * 2][0], sa + 2 * TILE + rb);
                ldsm4(&Bl[p * 2][0], sa + 3 * TILE + rb);
            }
#pragma unroll
            for (int mi = 0; mi < 2; mi++)
#pragma unroll
                for (int nj = 0; nj < 8; nj++)
                    mma_bf16(acc[mi][nj], Ah[mi], Bh[nj]);
#pragma unroll
            for (int mi = 0; mi < 2; mi++)
#pragma unroll
                for (int nj = 0; nj < 8; nj++)
                    mma_bf16(acc[mi][nj], Ah[mi], Bl[nj]);
#pragma unroll
            for (int mi = 0; mi < 2; mi++)
#pragma unroll
                for (int nj = 0; nj < 8; nj++)
                    mma_bf16(acc[mi][nj], Al[mi], Bh[nj]);
        }
        __syncthreads();
    }

    const int orow = bm + wm + (lane >> 2);
    const int ocol = bn + wn + (lane & 3) * 2;
#pragma unroll
    for (int mi = 0; mi < 2; mi++) {
        const int rA = orow + mi * 16;
#pragma unroll
        for (int nj = 0; nj < 8; nj++) {
            const int c = ocol + nj * 8;
            if (SPLIT) {
                uint32_t h0, l0, h1, l1;
                packsplit(h0, l0, acc[mi][nj][0], acc[mi][nj][1]);
                packsplit(h1, l1, acc[mi][nj][2], acc[mi][nj][3]);
                *reinterpret_cast<uint32_t*>(Chi + (size_t)rA * N + c)       = h0;
                *reinterpret_cast<uint32_t*>(Clo + (size_t)rA * N + c)       = l0;
                *reinterpret_cast<uint32_t*>(Chi + (size_t)(rA + 8) * N + c) = h1;
                *reinterpret_cast<uint32_t*>(Clo + (size_t)(rA + 8) * N + c) = l1;
            } else {
                float b0 = 0.f, b1 = 0.f;
                if (BIAS) { b0 = bias[c]; b1 = bias[c + 1]; }
                float2 v0, v1;
                v0.x = acc[mi][nj][0] + b0; v0.y = acc[mi][nj][1] + b1;
                v1.x = acc[mi][nj][2] + b0; v1.y = acc[mi][nj][3] + b1;
                *reinterpret_cast<float2*>(&C[(size_t)rA * N + c])       = v0;
                *reinterpret_cast<float2*>(&C[(size_t)(rA + 8) * N + c]) = v1;
            }
        }
    }
}

// ---------------------------------------------------------------------------
// Tensorized flash attention. Block = (128 q-rows, h, b); 256 threads = 8
// warps, each owning 16 q-rows. K-loop: 16 chunks of 64 keys, double-buffered.
// S = QK^T and O += P V both via 3-term bf16 mma. Online softmax on the
// m16n8 fragments (S accum layout == A fragment layout, so P packs in-regs).
// SMEM: Qhi|Qlo [128x144B] + 2 stages of (Khi|Klo|Vhi|Vlo)[64x144B] = 110592B.
// Output written as bf16 hi/lo for the proj GEMM.
// ---------------------------------------------------------------------------
__global__ __launch_bounds__(256)
void attn_mma(const __nv_bfloat16* __restrict__ qhi, const __nv_bfloat16* __restrict__ qlo,
              const float* __restrict__ atts,
              __nv_bfloat16* __restrict__ ohi, __nv_bfloat16* __restrict__ olo)
{
    extern __shared__ char smem[];
    const uint32_t sb = smem_u32(smem);
    const int SOFF = 36864, SSTAGE = 36864, TILE = 9216;

    const int tid = threadIdx.x, warp = tid >> 5, lane = tid & 31;
    const int qt = blockIdx.x, h = blockIdx.y, b = blockIdx.z;
    const int N = 1024, C3 = 3072;
    const float scale = 0.125f;

    const int aRow = (lane & 7) + ((lane & 8) ? 8 : 0);
    const int aKb  = (lane & 16) ? 16 : 0;
    const int bRow = (lane & 7) + ((lane & 16) ? 8 : 0);
    const int bKb  = (lane & 8) ? 16 : 0;

    // ---- load Q tiles (hi, lo) ----
    {
        size_t base = (size_t)(b * 1024 + qt * 128) * C3 + h * 64;
#pragma unroll
        for (int i = 0; i < 8; i++) {
            int idx = tid + i * 256;
            const __nv_bfloat16* src = (idx < 1024) ? qhi : qlo;
            int r = (idx >> 3) & 127, c = idx & 7;
            cp16(sb + (uint32_t)(idx >> 10) * 18432 + r * 144 + c * 16,
                 src + base + (size_t)r * C3 + c * 8);
        }
        CP_COMMIT();
    }

    auto load_stage = [&](int s, int ck) {
        size_t base = (size_t)(b * 1024 + ck * 64) * C3 + h * 64;
#pragma unroll
        for (int i = 0; i < 8; i++) {
            int idx = tid + i * 256;
            int t = idx >> 9, r = (idx >> 3) & 63, c = idx & 7;
            const __nv_bfloat16* src = (t & 1) ? qlo : qhi;
            size_t off = base + (size_t)r * C3 + c * 8 + ((t < 2) ? 1024 : 2048);
            cp16(sb + SOFF + s * SSTAGE + t * TILE + r * 144 + c * 16, src + off);
        }
        CP_COMMIT();
    };
    load_stage(0, 0);

    uint32_t Qh[4][4], Ql[4][4];
    float o[8][4];
#pragma unroll
    for (int nb = 0; nb < 8; nb++)
#pragma unroll
        for (int e = 0; e < 4; e++) o[nb][e] = 0.f;
    float m0 = -1e30f, m1 = -1e30f, l0 = 0.f, l1 = 0.f;

    const float* attsr0 = atts + (size_t)b * N * N
                        + (size_t)(qt * 128 + warp * 16 + (lane >> 2)) * N;
    const float* attsr8 = attsr0 + 8 * N;

    for (int ck = 0; ck < 16; ck++) {
        if (ck < 15) { load_stage((ck + 1) & 1, ck + 1); CP_WAIT(1); }
        else         { CP_WAIT(0); }
        __syncthreads();

        if (ck == 0) {
#pragma unroll
            for (int ks = 0; ks < 4; ks++) {
                uint32_t qa = sb + (uint32_t)((warp * 16 + aRow) * 144 + ks * 32 + aKb);
                ldsm4(Qh[ks], qa);
                ldsm4(Ql[ks], qa + 18432);
            }
        }

        const uint32_t kb_ = sb + SOFF + (uint32_t)(ck & 1) * SSTAGE;

        // ---- S = Q K^T (3-term) ----
        float s[8][4];
#pragma unroll
        for (int nb = 0; nb < 8; nb++)
#pragma unroll
            for (int e = 0; e < 4; e++) s[nb][e] = 0.f;

#pragma unroll
        for (int ks = 0; ks < 4; ks++) {
            uint32_t Kh[8][2], Kl[8][2];
#pragma unroll
            for (int p = 0; p < 4; p++) {
                uint32_t ka = kb_ + (uint32_t)((p * 16 + bRow) * 144 + ks * 32 + bKb);
                ldsm4(&Kh[p * 2][0], ka);
                ldsm4(&Kl[p * 2][0], ka + TILE);
            }
#pragma unroll
            for (int nb = 0; nb < 8; nb++) mma_bf16(s[nb], Qh[ks], Kh[nb]);
#pragma unroll
            for (int nb = 0; nb < 8; nb++) mma_bf16(s[nb], Qh[ks], Kl[nb]);
#pragma unroll
            for (int nb = 0; nb < 8; nb++) mma_bf16(s[nb], Ql[ks], Kh[nb]);
        }

        // ---- scale + mask ----
#pragma unroll
        for (int nb = 0; nb < 8; nb++) {
            int cb = ck * 64 + nb * 8 + (lane & 3) * 2;
            float2 ma = *reinterpret_cast<const float2*>(attsr0 + cb);
            float2 mb = *reinterpret_cast<const float2*>(attsr8 + cb);
            s[nb][0] = fmaf(s[nb][0], scale, ma.x);
            s[nb][1] = fmaf(s[nb][1], scale, ma.y);
            s[nb][2] = fmaf(s[nb][2], scale, mb.x);
            s[nb][3] = fmaf(s[nb][3], scale, mb.y);
        }

        // ---- online softmax (rows r = lane>>2 and r+8, cols across quad) ----
        float mx0 = -1e30f, mx1 = -1e30f;
#pragma unroll
        for (int nb = 0; nb < 8; nb++) {
            mx0 = fmaxf(mx0, fmaxf(s[nb][0], s[nb][1]));
            mx1 = fmaxf(mx1, fmaxf(s[nb][2], s[nb][3]));
        }
        mx0 = fmaxf(mx0, __shfl_xor_sync(0xffffffffu, mx0, 1, 32));
        mx0 = fmaxf(mx0, __shfl_xor_sync(0xffffffffu, mx0, 2, 32));
        mx1 = fmaxf(mx1, __shfl_xor_sync(0xffffffffu, mx1, 1, 32));
        mx1 = fmaxf(mx1, __shfl_xor_sync(0xffffffffu, mx1, 2, 32));
        float mn0 = fmaxf(m0, mx0), mn1 = fmaxf(m1, mx1);
        float al0 = __expf(m0 - mn0), al1 = __expf(m1 - mn1);
        m0 = mn0; m1 = mn1;

        float rs0 = 0.f, rs1 = 0.f;
#pragma unroll
        for (int nb = 0; nb < 8; nb++) {
            s[nb][0] = __expf(s[nb][0] - mn0);
            s[nb][1] = __expf(s[nb][1] - mn0);
            s[nb][2] = __expf(s[nb][2] - mn1);
            s[nb][3] = __expf(s[nb][3] - mn1);
            rs0 += s[nb][0] + s[nb][1];
            rs1 += s[nb][2] + s[nb][3];
        }
        rs0 += __shfl_xor_sync(0xffffffffu, rs0, 1, 32);
        rs0 += __shfl_xor_sync(0xffffffffu, rs0, 2, 32);
        rs1 += __shfl_xor_sync(0xffffffffu, rs1, 1, 32);
        rs1 += __shfl_xor_sync(0xffffffffu, rs1, 2, 32);
        l0 = l0 * al0 + rs0;
        l1 = l1 * al1 + rs1;

#pragma unroll
        for (int nb = 0; nb < 8; nb++) {
            o[nb][0] *= al0; o[nb][1] *= al0;
            o[nb][2] *= al1; o[nb][3] *= al1;
        }

        // ---- pack P -> A fragments (hi/lo) directly from S registers ----
        uint32_t Ph[4][4], Pl[4][4];
#pragma unroll
        for (int kb2 = 0; kb2 < 4; kb2++) {
            packsplit(Ph[kb2][0], Pl[kb2][0], s[2 * kb2][0],     s[2 * kb2][1]);
            packsplit(Ph[kb2][1], Pl[kb2][1], s[2 * kb2][2],     s[2 * kb2][3]);
            packsplit(Ph[kb2][2], Pl[kb2][2], s[2 * kb2 + 1][0], s[2 * kb2 + 1][1]);
            packsplit(Ph[kb2][3], Pl[kb2][3], s[2 * kb2 + 1][2], s[2 * kb2 + 1][3]);
        }

        // ---- O += P V (3-term; V via ldmatrix.trans) ----
        const uint32_t vb = kb_ + 2 * TILE;
#pragma unroll
        for (int kb2 = 0; kb2 < 4; kb2++) {
            uint32_t Vh[8][2], Vl[8][2];
#pragma unroll
            for (int p = 0; p < 4; p++) {
                uint32_t va = vb + (uint32_t)((kb2 * 16 + aRow) * 144 + p * 32 + aKb);
                ldsm4t(&Vh[p * 2][0], va);
                ldsm4t(&Vl[p * 2][0], va + TILE);
            }
#pragma unroll
            for (int nb = 0; nb < 8; nb++) mma_bf16(o[nb], Ph[kb2], Vh[nb]);
#pragma unroll
            for (int nb = 0; nb < 8; nb++) mma_bf16(o[nb], Ph[kb2], Vl[nb]);
#pragma unroll
            for (int nb = 0; nb < 8; nb++) mma_bf16(o[nb], Pl[kb2], Vh[nb]);
        }
        __syncthreads();
    }

    // ---- epilogue: normalize, split to bf16 hi/lo, store ----
    float i0 = 1.f / l0, i1 = 1.f / l1;
    size_t ro = (size_t)(b * 1024 + qt * 128 + warp * 16 + (lane >> 2)) * 1024 + h * 64;
#pragma unroll
    for (int nb = 0; nb < 8; nb++) {
        int col = nb * 8 + (lane & 3) * 2;
        uint32_t hh, ll;
        packsplit(hh, ll, o[nb][0] * i0, o[nb][1] * i0);
        *reinterpret_cast<uint32_t*>(ohi + ro + col) = hh;
        *reinterpret_cast<uint32_t*>(olo + ro + col) = ll;
        packsplit(hh, ll, o[nb][2] * i1, o[nb][3] * i1);
        *reinterpret_cast<uint32_t*>(ohi + ro + 8 * 1024 + col) = hh;
        *reinterpret_cast<uint32_t*>(olo + ro + 8 * 1024 + col) = ll;
    }
}

// ---------------------------------------------------------------------------
// Launch sequence
// inputs: 0 x, 1 text_embeds(unused), 2 image_atts, 3 qkv_w, 4 proj_w, 5 proj_b
// ---------------------------------------------------------------------------
extern "C" void kernel_launch(void* const* d_in, const int* in_sizes, int n_in,
                              void* d_out, int out_size)
{
    (void)in_sizes; (void)n_in; (void)out_size;
    const float* x      = (const float*)d_in[0];
    const float* atts   = (const float*)d_in[2];
    const float* qkv_w  = (const float*)d_in[3];
    const float* proj_w = (const float*)d_in[4];
    const float* proj_b = (const float*)d_in[5];
    float* out = (float*)d_out;

    __nv_bfloat16 *qkvhi, *qkvlo, *xhi, *xlo, *w1hi, *w1lo, *ahi, *alo, *w2hi, *w2lo;
    cudaGetSymbolAddress((void**)&qkvhi, g_qkvhi);
    cudaGetSymbolAddress((void**)&qkvlo, g_qkvlo);
    cudaGetSymbolAddress((void**)&xhi,  g_xhi);
    cudaGetSymbolAddress((void**)&xlo,  g_xlo);
    cudaGetSymbolAddress((void**)&w1hi, g_w1hi);
    cudaGetSymbolAddress((void**)&w1lo, g_w1lo);
    cudaGetSymbolAddress((void**)&ahi,  g_ahi);
    cudaGetSymbolAddress((void**)&alo,  g_alo);
    cudaGetSymbolAddress((void**)&w2hi, g_w2hi);
    cudaGetSymbolAddress((void**)&w2lo, g_w2lo);

    cudaFuncSetAttribute(gemm_mma<false, true>, cudaFuncAttributeMaxDynamicSharedMemorySize, 81920);
    cudaFuncSetAttribute(gemm_mma<true, false>, cudaFuncAttributeMaxDynamicSharedMemorySize, 81920);
    cudaFuncSetAttribute(attn_mma, cudaFuncAttributeMaxDynamicSharedMemorySize, 110592);

    // 1) split x; transpose+split weights
    split_kernel<<<8192, 256>>>(x, xhi, xlo, 8192 * 1024 / 4);
    tsplit_kernel<<<dim3(96, 32), dim3(32, 8)>>>(qkv_w, w1hi, w1lo, 1024, 3072);
    tsplit_kernel<<<dim3(32, 32), dim3(32, 8)>>>(proj_w, w2hi, w2lo, 1024, 1024);

    // 2) qkv = x @ qkv_w  (HMMA 3-term, bf16 hi/lo output)
    gemm_mma<false, true><<<dim3(24, 64), 256, 81920>>>(
        xhi, xlo, w1hi, w1lo, nullptr, nullptr, qkvhi, qkvlo, 8192, 3072, 1024);

    // 3) tensorized flash attention (bf16 hi/lo in and out)
    attn_mma<<<dim3(8, 16, 8), 256, 110592>>>(qkvhi, qkvlo, atts, ahi, alo);

    // 4) out = attn @ proj_w + bias  (HMMA 3-term, fp32 output)
    gemm_mma<true, false><<<dim3(8, 64), 256, 81920>>>(
        ahi, alo, w2hi, w2lo, proj_b, out, nullptr, nullptr, 8192, 1024, 1024);
}

// round 10
// speedup vs baseline: 2.3743x; 1.0511x over previous
#include <cuda_runtime.h>
#include <cuda_bf16.h>
#include <cstdint>

// ===========================================================================
// Attention block, GB300 (sm_103 ptxas target -> portable mma.sync HMMA).
// Round 10: GEMM SMEM relayout -> hi|lo interleaved 128B rows + XOR swizzle
// (stage 32KB, 2 stages = 64KB) + __launch_bounds__(256,2) for 2 CTA/SM.
// Attention unchanged from round 9 (passing).
// ===========================================================================

// ---- scratch (device globals; no allocations allowed) ---------------------
__device__ __nv_bfloat16 g_qkvhi[8192ull * 3072];  // gemm1 out hi
__device__ __nv_bfloat16 g_qkvlo[8192ull * 3072];  // gemm1 out lo
__device__ __nv_bfloat16 g_xhi [8192ull * 1024];
__device__ __nv_bfloat16 g_xlo [8192ull * 1024];
__device__ __nv_bfloat16 g_w1hi[3072ull * 1024];   // qkv_w^T split, [N,K]
__device__ __nv_bfloat16 g_w1lo[3072ull * 1024];
__device__ __nv_bfloat16 g_ahi [8192ull * 1024];   // attention out hi
__device__ __nv_bfloat16 g_alo [8192ull * 1024];   // attention out lo
__device__ __nv_bfloat16 g_w2hi[1024ull * 1024];   // proj_w^T split, [N,K]
__device__ __nv_bfloat16 g_w2lo[1024ull * 1024];

// ---- ptx helpers ----------------------------------------------------------
__device__ __forceinline__ uint32_t smem_u32(const void* p) {
    uint32_t a;
    asm("{ .reg .u64 t; cvta.to.shared.u64 t, %1; cvt.u32.u64 %0, t; }"
        : "=r"(a) : "l"(p));
    return a;
}

__device__ __forceinline__ void cp16(uint32_t saddr, const void* g) {
    asm volatile("cp.async.cg.shared.global [%0], [%1], 16;"
                 :: "r"(saddr), "l"(g));
}
#define CP_COMMIT() asm volatile("cp.async.commit_group;" ::: "memory")
#define CP_WAIT(n)  asm volatile("cp.async.wait_group %0;" :: "n"(n) : "memory")

__device__ __forceinline__ void ldsm4(uint32_t* r, uint32_t addr) {
    asm volatile("ldmatrix.sync.aligned.m8n8.x4.shared.b16 {%0,%1,%2,%3}, [%4];"
                 : "=r"(r[0]), "=r"(r[1]), "=r"(r[2]), "=r"(r[3]) : "r"(addr));
}
__device__ __forceinline__ void ldsm4t(uint32_t* r, uint32_t addr) {
    asm volatile("ldmatrix.sync.aligned.m8n8.x4.trans.shared.b16 {%0,%1,%2,%3}, [%4];"
                 : "=r"(r[0]), "=r"(r[1]), "=r"(r[2]), "=r"(r[3]) : "r"(addr));
}

__device__ __forceinline__ void mma_bf16(float* d, const uint32_t* a, const uint32_t* b) {
    asm volatile("mma.sync.aligned.m16n8k16.row.col.f32.bf16.bf16.f32 "
                 "{%0,%1,%2,%3}, {%4,%5,%6,%7}, {%8,%9}, {%0,%1,%2,%3};"
                 : "+f"(d[0]), "+f"(d[1]), "+f"(d[2]), "+f"(d[3])
                 : "r"(a[0]), "r"(a[1]), "r"(a[2]), "r"(a[3]),
                   "r"(b[0]), "r"(b[1]));
}

// pack two fp32 -> bf16x2 hi + bf16x2 residual lo (e0 in low halves)
__device__ __forceinline__ void packsplit(uint32_t& hi, uint32_t& lo, float e0, float e1) {
    uint32_t h;
    asm("cvt.rn.bf16x2.f32 %0, %1, %2;" : "=r"(h) : "f"(e1), "f"(e0));
    float f0 = __uint_as_float(h << 16);
    float f1 = __uint_as_float(h & 0xffff0000u);
    uint32_t l;
    asm("cvt.rn.bf16x2.f32 %0, %1, %2;" : "=r"(l) : "f"(e1 - f1), "f"(e0 - f0));
    hi = h; lo = l;
}

// ---------------------------------------------------------------------------
// fp32 -> bf16 hi/lo split (elementwise, vectorized x4)
// ---------------------------------------------------------------------------
__global__ __launch_bounds__(256)
void split_kernel(const float* __restrict__ in, __nv_bfloat16* __restrict__ hi,
                  __nv_bfloat16* __restrict__ lo, int n4)
{
    int i = blockIdx.x * 256 + threadIdx.x;
    if (i >= n4) return;
    float4 v = reinterpret_cast<const float4*>(in)[i];
    __nv_bfloat16 h[4], l[4];
    float f[4] = {v.x, v.y, v.z, v.w};
#pragma unroll
    for (int j = 0; j < 4; j++) {
        h[j] = __float2bfloat16(f[j]);
        l[j] = __float2bfloat16(f[j] - __bfloat162float(h[j]));
    }
    reinterpret_cast<uint2*>(hi)[i] = *reinterpret_cast<uint2*>(h);
    reinterpret_cast<uint2*>(lo)[i] = *reinterpret_cast<uint2*>(l);
}

// ---------------------------------------------------------------------------
// W[K,N] fp32 -> W^T[N,K] bf16 hi/lo  (tiled transpose + split)
// ---------------------------------------------------------------------------
__global__ __launch_bounds__(256)
void tsplit_kernel(const float* __restrict__ W, __nv_bfloat16* __restrict__ hi,
                   __nv_bfloat16* __restrict__ lo, int K, int N)
{
    __shared__ float tile[32][33];
    int tx = threadIdx.x, ty = threadIdx.y;
    int bn = blockIdx.x * 32, bk = blockIdx.y * 32;
#pragma unroll
    for (int r = 0; r < 4; r++)
        tile[ty + r * 8][tx] = W[(size_t)(bk + ty + r * 8) * N + bn + tx];
    __syncthreads();
#pragma unroll
    for (int r = 0; r < 4; r++) {
        int n = bn + ty + r * 8;
        int k = bk + tx;
        float a = tile[tx][ty + r * 8];
        __nv_bfloat16 h = __float2bfloat16(a);
        hi[(size_t)n * K + k] = h;
        lo[(size_t)n * K + k] = __float2bfloat16(a - __bfloat162float(h));
    }
}

// ---------------------------------------------------------------------------
// HMMA GEMM: C = (Ahi+Alo) @ (Bhi+Blo)^T (+bias). 128x128 CTA, 8 warps,
// K-chunk 32, double-buffered cp.async.
// SMEM layout (new): per tile 128 rows x 128B; row = [hi k0..31 | lo k0..31],
// chunk swizzle c' = c ^ (row&7) -> conflict-free ldmatrix, zero padding.
// Stage = A tile 16KB + B tile 16KB = 32KB; 2 stages = 64KB -> 2 CTA/SM.
// SPLIT=true: write bf16 hi/lo (Chi/Clo) instead of fp32 C.
// ---------------------------------------------------------------------------
template<bool BIAS, bool SPLIT>
__global__ __launch_bounds__(256, 2)
void gemm_mma(const __nv_bfloat16* __restrict__ Ahi, const __nv_bfloat16* __restrict__ Alo,
              const __nv_bfloat16* __restrict__ Bhi, const __nv_bfloat16* __restrict__ Blo,
              const float* __restrict__ bias, float* __restrict__ C,
              __nv_bfloat16* __restrict__ Chi, __nv_bfloat16* __restrict__ Clo,
              int M, int N, int K)
{
    extern __shared__ char smem[];
    const uint32_t sbase = smem_u32(smem);
    const int STAGE = 32768, TILE = 16384;

    const int tid  = threadIdx.x;
    const int warp = tid >> 5;
    const int lane = tid & 31;
    const int bm = blockIdx.y << 7;
    const int bn = blockIdx.x << 7;

    const int wm = (warp & 3) * 32;
    const int wn = (warp >> 2) * 64;

    // ldmatrix lane decomposition
    const int aRow = (lane & 7) + ((lane & 8) ? 8 : 0);   // row within 16
    const int aCh  = (lane & 16) ? 1 : 0;                 // k 16B-chunk select
    const int bRow = (lane & 7) + ((lane & 16) ? 8 : 0);
    const int bCh  = (lane & 8) ? 1 : 0;

    float acc[2][8][4];
#pragma unroll
    for (int mi = 0; mi < 2; mi++)
#pragma unroll
        for (int nj = 0; nj < 8; nj++)
#pragma unroll
            for (int e = 0; e < 4; e++) acc[mi][nj][e] = 0.f;

    const int nk = K >> 5;

    // stage loader: 2048 16B-chunks (A 1024 + B 1024), 8 per thread
    auto load_stage = [&](int s, int k0) {
        uint32_t sa = sbase + s * STAGE;
#pragma unroll
        for (int i = 0; i < 8; i++) {
            int idx  = tid + i * 256;
            int tile = idx >> 10;                 // 0 = A, 1 = B
            int row  = (idx >> 3) & 127;
            int c    = idx & 7;                   // 0-3 hi, 4-7 lo
            const __nv_bfloat16* src =
                (tile == 0) ? ((c < 4) ? Ahi : Alo) : ((c < 4) ? Bhi : Blo);
            int rowg = ((tile == 0) ? bm : bn) + row;
            int kk   = k0 + (c & 3) * 8;
            uint32_t dst = sa + (uint32_t)(tile * TILE + row * 128
                                           + ((c ^ (row & 7)) * 16));
            cp16(dst, src + (size_t)rowg * K + kk);
        }
        CP_COMMIT();
    };

    load_stage(0, 0);

    for (int ch = 0; ch < nk; ch++) {
        const uint32_t sa = sbase + (ch & 1) * STAGE;
        if (ch + 1 < nk) { load_stage((ch + 1) & 1, (ch + 1) << 5); CP_WAIT(1); }
        else             { CP_WAIT(0); }
        __syncthreads();

#pragma unroll
        for (int ks = 0; ks < 2; ks++) {
            uint32_t Ah[2][4], Al[2][4], Bh[8][2], Bl[8][2];
#pragma unroll
            for (int mi = 0; mi < 2; mi++) {
                int row  = wm + mi * 16 + aRow;
                int cHi  = (2 * ks + aCh) ^ (row & 7);
                int cLo  = (4 + 2 * ks + aCh) ^ (row & 7);
                ldsm4(Ah[mi], sa + (uint32_t)(row * 128 + cHi * 16));
                ldsm4(Al[mi], sa + (uint32_t)(row * 128 + cLo * 16));
            }
#pragma unroll
            for (int p = 0; p < 4; p++) {
                int row  = wn + p * 16 + bRow;
                int cHi  = (2 * ks + bCh) ^ (row & 7);
                int cLo  = (4 + 2 * ks + bCh) ^ (row & 7);
                ldsm4(&Bh[p * 2][0], sa + (uint32_t)(TILE + row * 128 + cHi * 16));
                ldsm4(&Bl[p * 2][0], sa + (uint32_t)(TILE + row * 128 + cLo * 16));
            }
#pragma unroll
            for (int mi = 0; mi < 2; mi++)
#pragma unroll
                for (int nj = 0; nj < 8; nj++)
                    mma_bf16(acc[mi][nj], Ah[mi], Bh[nj]);
#pragma unroll
            for (int mi = 0; mi < 2; mi++)
#pragma unroll
                for (int nj = 0; nj < 8; nj++)
                    mma_bf16(acc[mi][nj], Ah[mi], Bl[nj]);
#pragma unroll
            for (int mi = 0; mi < 2; mi++)
#pragma unroll
                for (int nj = 0; nj < 8; nj++)
                    mma_bf16(acc[mi][nj], Al[mi], Bh[nj]);
        }
        __syncthreads();
    }

    const int orow = bm + wm + (lane >> 2);
    const int ocol = bn + wn + (lane & 3) * 2;
#pragma unroll
    for (int mi = 0; mi < 2; mi++) {
        const int rA = orow + mi * 16;
#pragma unroll
        for (int nj = 0; nj < 8; nj++) {
            const int c = ocol + nj * 8;
            if (SPLIT) {
                uint32_t h0, l0, h1, l1;
                packsplit(h0, l0, acc[mi][nj][0], acc[mi][nj][1]);
                packsplit(h1, l1, acc[mi][nj][2], acc[mi][nj][3]);
                *reinterpret_cast<uint32_t*>(Chi + (size_t)rA * N + c)       = h0;
                *reinterpret_cast<uint32_t*>(Clo + (size_t)rA * N + c)       = l0;
                *reinterpret_cast<uint32_t*>(Chi + (size_t)(rA + 8) * N + c) = h1;
                *reinterpret_cast<uint32_t*>(Clo + (size_t)(rA + 8) * N + c) = l1;
            } else {
                float b0 = 0.f, b1 = 0.f;
                if (BIAS) { b0 = bias[c]; b1 = bias[c + 1]; }
                float2 v0, v1;
                v0.x = acc[mi][nj][0] + b0; v0.y = acc[mi][nj][1] + b1;
                v1.x = acc[mi][nj][2] + b0; v1.y = acc[mi][nj][3] + b1;
                *reinterpret_cast<float2*>(&C[(size_t)rA * N + c])       = v0;
                *reinterpret_cast<float2*>(&C[(size_t)(rA + 8) * N + c]) = v1;
            }
        }
    }
}

// ---------------------------------------------------------------------------
// Tensorized flash attention (unchanged from round 9, passing).
// ---------------------------------------------------------------------------
__global__ __launch_bounds__(256)
void attn_mma(const __nv_bfloat16* __restrict__ qhi, const __nv_bfloat16* __restrict__ qlo,
              const float* __restrict__ atts,
              __nv_bfloat16* __restrict__ ohi, __nv_bfloat16* __restrict__ olo)
{
    extern __shared__ char smem[];
    const uint32_t sb = smem_u32(smem);
    const int SOFF = 36864, SSTAGE = 36864, TILE = 9216;

    const int tid = threadIdx.x, warp = tid >> 5, lane = tid & 31;
    const int qt = blockIdx.x, h = blockIdx.y, b = blockIdx.z;
    const int N = 1024, C3 = 3072;
    const float scale = 0.125f;

    const int aRow = (lane & 7) + ((lane & 8) ? 8 : 0);
    const int aKb  = (lane & 16) ? 16 : 0;
    const int bRow = (lane & 7) + ((lane & 16) ? 8 : 0);
    const int bKb  = (lane & 8) ? 16 : 0;

    // ---- load Q tiles (hi, lo) ----
    {
        size_t base = (size_t)(b * 1024 + qt * 128) * C3 + h * 64;
#pragma unroll
        for (int i = 0; i < 8; i++) {
            int idx = tid + i * 256;
            const __nv_bfloat16* src = (idx < 1024) ? qhi : qlo;
            int r = (idx >> 3) & 127, c = idx & 7;
            cp16(sb + (uint32_t)(idx >> 10) * 18432 + r * 144 + c * 16,
                 src + base + (size_t)r * C3 + c * 8);
        }
        CP_COMMIT();
    }

    auto load_stage = [&](int s, int ck) {
        size_t base = (size_t)(b * 1024 + ck * 64) * C3 + h * 64;
#pragma unroll
        for (int i = 0; i < 8; i++) {
            int idx = tid + i * 256;
            int t = idx >> 9, r = (idx >> 3) & 63, c = idx & 7;
            const __nv_bfloat16* src = (t & 1) ? qlo : qhi;
            size_t off = base + (size_t)r * C3 + c * 8 + ((t < 2) ? 1024 : 2048);
            cp16(sb + SOFF + s * SSTAGE + t * TILE + r * 144 + c * 16, src + off);
        }
        CP_COMMIT();
    };
    load_stage(0, 0);

    uint32_t Qh[4][4], Ql[4][4];
    float o[8][4];
#pragma unroll
    for (int nb = 0; nb < 8; nb++)
#pragma unroll
        for (int e = 0; e < 4; e++) o[nb][e] = 0.f;
    float m0 = -1e30f, m1 = -1e30f, l0 = 0.f, l1 = 0.f;

    const float* attsr0 = atts + (size_t)b * N * N
                        + (size_t)(qt * 128 + warp * 16 + (lane >> 2)) * N;
    const float* attsr8 = attsr0 + 8 * N;

    for (int ck = 0; ck < 16; ck++) {
        if (ck < 15) { load_stage((ck + 1) & 1, ck + 1); CP_WAIT(1); }
        else         { CP_WAIT(0); }
        __syncthreads();

        if (ck == 0) {
#pragma unroll
            for (int ks = 0; ks < 4; ks++) {
                uint32_t qa = sb + (uint32_t)((warp * 16 + aRow) * 144 + ks * 32 + aKb);
                ldsm4(Qh[ks], qa);
                ldsm4(Ql[ks], qa + 18432);
            }
        }

        const uint32_t kb_ = sb + SOFF + (uint32_t)(ck & 1) * SSTAGE;

        // ---- S = Q K^T (3-term) ----
        float s[8][4];
#pragma unroll
        for (int nb = 0; nb < 8; nb++)
#pragma unroll
            for (int e = 0; e < 4; e++) s[nb][e] = 0.f;

#pragma unroll
        for (int ks = 0; ks < 4; ks++) {
            uint32_t Kh[8][2], Kl[8][2];
#pragma unroll
            for (int p = 0; p < 4; p++) {
                uint32_t ka = kb_ + (uint32_t)((p * 16 + bRow) * 144 + ks * 32 + bKb);
                ldsm4(&Kh[p * 2][0], ka);
                ldsm4(&Kl[p * 2][0], ka + TILE);
            }
#pragma unroll
            for (int nb = 0; nb < 8; nb++) mma_bf16(s[nb], Qh[ks], Kh[nb]);
#pragma unroll
            for (int nb = 0; nb < 8; nb++) mma_bf16(s[nb], Qh[ks], Kl[nb]);
#pragma unroll
            for (int nb = 0; nb < 8; nb++) mma_bf16(s[nb], Ql[ks], Kh[nb]);
        }

        // ---- scale + mask ----
#pragma unroll
        for (int nb = 0; nb < 8; nb++) {
            int cb = ck * 64 + nb * 8 + (lane & 3) * 2;
            float2 ma = *reinterpret_cast<const float2*>(attsr0 + cb);
            float2 mb = *reinterpret_cast<const float2*>(attsr8 + cb);
            s[nb][0] = fmaf(s[nb][0], scale, ma.x);
            s[nb][1] = fmaf(s[nb][1], scale, ma.y);
            s[nb][2] = fmaf(s[nb][2], scale, mb.x);
            s[nb][3] = fmaf(s[nb][3], scale, mb.y);
        }

        // ---- online softmax ----
        float mx0 = -1e30f, mx1 = -1e30f;
#pragma unroll
        for (int nb = 0; nb < 8; nb++) {
            mx0 = fmaxf(mx0, fmaxf(s[nb][0], s[nb][1]));
            mx1 = fmaxf(mx1, fmaxf(s[nb][2], s[nb][3]));
        }
        mx0 = fmaxf(mx0, __shfl_xor_sync(0xffffffffu, mx0, 1, 32));
        mx0 = fmaxf(mx0, __shfl_xor_sync(0xffffffffu, mx0, 2, 32));
        mx1 = fmaxf(mx1, __shfl_xor_sync(0xffffffffu, mx1, 1, 32));
        mx1 = fmaxf(mx1, __shfl_xor_sync(0xffffffffu, mx1, 2, 32));
        float mn0 = fmaxf(m0, mx0), mn1 = fmaxf(m1, mx1);
        float al0 = __expf(m0 - mn0), al1 = __expf(m1 - mn1);
        m0 = mn0; m1 = mn1;

        float rs0 = 0.f, rs1 = 0.f;
#pragma unroll
        for (int nb = 0; nb < 8; nb++) {
            s[nb][0] = __expf(s[nb][0] - mn0);
            s[nb][1] = __expf(s[nb][1] - mn0);
            s[nb][2] = __expf(s[nb][2] - mn1);
            s[nb][3] = __expf(s[nb][3] - mn1);
            rs0 += s[nb][0] + s[nb][1];
            rs1 += s[nb][2] + s[nb][3];
        }
        rs0 += __shfl_xor_sync(0xffffffffu, rs0, 1, 32);
        rs0 += __shfl_xor_sync(0xffffffffu, rs0, 2, 32);
        rs1 += __shfl_xor_sync(0xffffffffu, rs1, 1, 32);
        rs1 += __shfl_xor_sync(0xffffffffu, rs1, 2, 32);
        l0 = l0 * al0 + rs0;
        l1 = l1 * al1 + rs1;

#pragma unroll
        for (int nb = 0; nb < 8; nb++) {
            o[nb][0] *= al0; o[nb][1] *= al0;
            o[nb][2] *= al1; o[nb][3] *= al1;
        }

        // ---- pack P -> A fragments (hi/lo) ----
        uint32_t Ph[4][4], Pl[4][4];
#pragma unroll
        for (int kb2 = 0; kb2 < 4; kb2++) {
            packsplit(Ph[kb2][0], Pl[kb2][0], s[2 * kb2][0],     s[2 * kb2][1]);
            packsplit(Ph[kb2][1], Pl[kb2][1], s[2 * kb2][2],     s[2 * kb2][3]);
            packsplit(Ph[kb2][2], Pl[kb2][2], s[2 * kb2 + 1][0], s[2 * kb2 + 1][1]);
            packsplit(Ph[kb2][3], Pl[kb2][3], s[2 * kb2 + 1][2], s[2 * kb2 + 1][3]);
        }

        // ---- O += P V (3-term; V via ldmatrix.trans) ----
        const uint32_t vb = kb_ + 2 * TILE;
#pragma unroll
        for (int kb2 = 0; kb2 < 4; kb2++) {
            uint32_t Vh[8][2], Vl[8][2];
#pragma unroll
            for (int p = 0; p < 4; p++) {
                uint32_t va = vb + (uint32_t)((kb2 * 16 + aRow) * 144 + p * 32 + aKb);
                ldsm4t(&Vh[p * 2][0], va);
                ldsm4t(&Vl[p * 2][0], va + TILE);
            }
#pragma unroll
            for (int nb = 0; nb < 8; nb++) mma_bf16(o[nb], Ph[kb2], Vh[nb]);
#pragma unroll
            for (int nb = 0; nb < 8; nb++) mma_bf16(o[nb], Ph[kb2], Vl[nb]);
#pragma unroll
            for (int nb = 0; nb < 8; nb++) mma_bf16(o[nb], Pl[kb2], Vh[nb]);
        }
        __syncthreads();
    }

    // ---- epilogue: normalize, split to bf16 hi/lo, store ----
    float i0 = 1.f / l0, i1 = 1.f / l1;
    size_t ro = (size_t)(b * 1024 + qt * 128 + warp * 16 + (lane >> 2)) * 1024 + h * 64;
#pragma unroll
    for (int nb = 0; nb < 8; nb++) {
        int col = nb * 8 + (lane & 3) * 2;
        uint32_t hh, ll;
        packsplit(hh, ll, o[nb][0] * i0, o[nb][1] * i0);
        *reinterpret_cast<uint32_t*>(ohi + ro + col) = hh;
        *reinterpret_cast<uint32_t*>(olo + ro + col) = ll;
        packsplit(hh, ll, o[nb][2] * i1, o[nb][3] * i1);
        *reinterpret_cast<uint32_t*>(ohi + ro + 8 * 1024 + col) = hh;
        *reinterpret_cast<uint32_t*>(olo + ro + 8 * 1024 + col) = ll;
    }
}

// ---------------------------------------------------------------------------
// Launch sequence
// inputs: 0 x, 1 text_embeds(unused), 2 image_atts, 3 qkv_w, 4 proj_w, 5 proj_b
// ---------------------------------------------------------------------------
extern "C" void kernel_launch(void* const* d_in, const int* in_sizes, int n_in,
                              void* d_out, int out_size)
{
    (void)in_sizes; (void)n_in; (void)out_size;
    const float* x      = (const float*)d_in[0];
    const float* atts   = (const float*)d_in[2];
    const float* qkv_w  = (const float*)d_in[3];
    const float* proj_w = (const float*)d_in[4];
    const float* proj_b = (const float*)d_in[5];
    float* out = (float*)d_out;

    __nv_bfloat16 *qkvhi, *qkvlo, *xhi, *xlo, *w1hi, *w1lo, *ahi, *alo, *w2hi, *w2lo;
    cudaGetSymbolAddress((void**)&qkvhi, g_qkvhi);
    cudaGetSymbolAddress((void**)&qkvlo, g_qkvlo);
    cudaGetSymbolAddress((void**)&xhi,  g_xhi);
    cudaGetSymbolAddress((void**)&xlo,  g_xlo);
    cudaGetSymbolAddress((void**)&w1hi, g_w1hi);
    cudaGetSymbolAddress((void**)&w1lo, g_w1lo);
    cudaGetSymbolAddress((void**)&ahi,  g_ahi);
    cudaGetSymbolAddress((void**)&alo,  g_alo);
    cudaGetSymbolAddress((void**)&w2hi, g_w2hi);
    cudaGetSymbolAddress((void**)&w2lo, g_w2lo);

    cudaFuncSetAttribute(gemm_mma<false, true>, cudaFuncAttributeMaxDynamicSharedMemorySize, 65536);
    cudaFuncSetAttribute(gemm_mma<true, false>, cudaFuncAttributeMaxDynamicSharedMemorySize, 65536);
    cudaFuncSetAttribute(attn_mma, cudaFuncAttributeMaxDynamicSharedMemorySize, 110592);

    // 1) split x; transpose+split weights
    split_kernel<<<8192, 256>>>(x, xhi, xlo, 8192 * 1024 / 4);
    tsplit_kernel<<<dim3(96, 32), dim3(32, 8)>>>(qkv_w, w1hi, w1lo, 1024, 3072);
    tsplit_kernel<<<dim3(32, 32), dim3(32, 8)>>>(proj_w, w2hi, w2lo, 1024, 1024);

    // 2) qkv = x @ qkv_w  (HMMA 3-term, bf16 hi/lo output)
    gemm_mma<false, true><<<dim3(24, 64), 256, 65536>>>(
        xhi, xlo, w1hi, w1lo, nullptr, nullptr, qkvhi, qkvlo, 8192, 3072, 1024);

    // 3) tensorized flash attention (bf16 hi/lo in and out)
    attn_mma<<<dim3(8, 16, 8), 256, 110592>>>(qkvhi, qkvlo, atts, ahi, alo);

    // 4) out = attn @ proj_w + bias  (HMMA 3-term, fp32 output)
    gemm_mma<true, false><<<dim3(8, 64), 256, 65536>>>(
        ahi, alo, w2hi, w2lo, proj_b, out, nullptr, nullptr, 8192, 1024, 1024);
}

// round 12
// speedup vs baseline: 2.5871x; 1.0896x over previous
#include <cuda_runtime.h>
#include <cuda_bf16.h>
#include <cstdint>

// ===========================================================================
// Attention block, GB300 (sm_103 ptxas target -> portable mma.sync HMMA).
// Round 12 (= round-11 resubmit; infra timeout): GEMM -> 3-stage cp.async
// pipeline with ONE __syncthreads per K-chunk. Attention ->
// __launch_bounds__(256,2) doubling resident warps.
// ===========================================================================

// ---- scratch (device globals; no allocations allowed) ---------------------
__device__ __nv_bfloat16 g_qkvhi[8192ull * 3072];  // gemm1 out hi
__device__ __nv_bfloat16 g_qkvlo[8192ull * 3072];  // gemm1 out lo
__device__ __nv_bfloat16 g_xhi [8192ull * 1024];
__device__ __nv_bfloat16 g_xlo [8192ull * 1024];
__device__ __nv_bfloat16 g_w1hi[3072ull * 1024];   // qkv_w^T split, [N,K]
__device__ __nv_bfloat16 g_w1lo[3072ull * 1024];
__device__ __nv_bfloat16 g_ahi [8192ull * 1024];   // attention out hi
__device__ __nv_bfloat16 g_alo [8192ull * 1024];   // attention out lo
__device__ __nv_bfloat16 g_w2hi[1024ull * 1024];   // proj_w^T split, [N,K]
__device__ __nv_bfloat16 g_w2lo[1024ull * 1024];

// ---- ptx helpers ----------------------------------------------------------
__device__ __forceinline__ uint32_t smem_u32(const void* p) {
    uint32_t a;
    asm("{ .reg .u64 t; cvta.to.shared.u64 t, %1; cvt.u32.u64 %0, t; }"
        : "=r"(a) : "l"(p));
    return a;
}

__device__ __forceinline__ void cp16(uint32_t saddr, const void* g) {
    asm volatile("cp.async.cg.shared.global [%0], [%1], 16;"
                 :: "r"(saddr), "l"(g));
}
#define CP_COMMIT() asm volatile("cp.async.commit_group;" ::: "memory")
#define CP_WAIT(n)  asm volatile("cp.async.wait_group %0;" :: "n"(n) : "memory")

__device__ __forceinline__ void ldsm4(uint32_t* r, uint32_t addr) {
    asm volatile("ldmatrix.sync.aligned.m8n8.x4.shared.b16 {%0,%1,%2,%3}, [%4];"
                 : "=r"(r[0]), "=r"(r[1]), "=r"(r[2]), "=r"(r[3]) : "r"(addr));
}
__device__ __forceinline__ void ldsm4t(uint32_t* r, uint32_t addr) {
    asm volatile("ldmatrix.sync.aligned.m8n8.x4.trans.shared.b16 {%0,%1,%2,%3}, [%4];"
                 : "=r"(r[0]), "=r"(r[1]), "=r"(r[2]), "=r"(r[3]) : "r"(addr));
}

__device__ __forceinline__ void mma_bf16(float* d, const uint32_t* a, const uint32_t* b) {
    asm volatile("mma.sync.aligned.m16n8k16.row.col.f32.bf16.bf16.f32 "
                 "{%0,%1,%2,%3}, {%4,%5,%6,%7}, {%8,%9}, {%0,%1,%2,%3};"
                 : "+f"(d[0]), "+f"(d[1]), "+f"(d[2]), "+f"(d[3])
                 : "r"(a[0]), "r"(a[1]), "r"(a[2]), "r"(a[3]),
                   "r"(b[0]), "r"(b[1]));
}

// pack two fp32 -> bf16x2 hi + bf16x2 residual lo (e0 in low halves)
__device__ __forceinline__ void packsplit(uint32_t& hi, uint32_t& lo, float e0, float e1) {
    uint32_t h;
    asm("cvt.rn.bf16x2.f32 %0, %1, %2;" : "=r"(h) : "f"(e1), "f"(e0));
    float f0 = __uint_as_float(h << 16);
    float f1 = __uint_as_float(h & 0xffff0000u);
    uint32_t l;
    asm("cvt.rn.bf16x2.f32 %0, %1, %2;" : "=r"(l) : "f"(e1 - f1), "f"(e0 - f0));
    hi = h; lo = l;
}

// ---------------------------------------------------------------------------
// fp32 -> bf16 hi/lo split (elementwise, vectorized x4)
// ---------------------------------------------------------------------------
__global__ __launch_bounds__(256)
void split_kernel(const float* __restrict__ in, __nv_bfloat16* __restrict__ hi,
                  __nv_bfloat16* __restrict__ lo, int n4)
{
    int i = blockIdx.x * 256 + threadIdx.x;
    if (i >= n4) return;
    float4 v = reinterpret_cast<const float4*>(in)[i];
    __nv_bfloat16 h[4], l[4];
    float f[4] = {v.x, v.y, v.z, v.w};
#pragma unroll
    for (int j = 0; j < 4; j++) {
        h[j] = __float2bfloat16(f[j]);
        l[j] = __float2bfloat16(f[j] - __bfloat162float(h[j]));
    }
    reinterpret_cast<uint2*>(hi)[i] = *reinterpret_cast<uint2*>(h);
    reinterpret_cast<uint2*>(lo)[i] = *reinterpret_cast<uint2*>(l);
}

// ---------------------------------------------------------------------------
// W[K,N] fp32 -> W^T[N,K] bf16 hi/lo  (tiled transpose + split)
// ---------------------------------------------------------------------------
__global__ __launch_bounds__(256)
void tsplit_kernel(const float* __restrict__ W, __nv_bfloat16* __restrict__ hi,
                   __nv_bfloat16* __restrict__ lo, int K, int N)
{
    __shared__ float tile[32][33];
    int tx = threadIdx.x, ty = threadIdx.y;
    int bn = blockIdx.x * 32, bk = blockIdx.y * 32;
#pragma unroll
    for (int r = 0; r < 4; r++)
        tile[ty + r * 8][tx] = W[(size_t)(bk + ty + r * 8) * N + bn + tx];
    __syncthreads();
#pragma unroll
    for (int r = 0; r < 4; r++) {
        int n = bn + ty + r * 8;
        int k = bk + tx;
        float a = tile[tx][ty + r * 8];
        __nv_bfloat16 h = __float2bfloat16(a);
        hi[(size_t)n * K + k] = h;
        lo[(size_t)n * K + k] = __float2bfloat16(a - __bfloat162float(h));
    }
}

// ---------------------------------------------------------------------------
// HMMA GEMM: C = (Ahi+Alo) @ (Bhi+Blo)^T (+bias). 128x128 CTA, 8 warps,
// K-chunk 32, THREE-stage cp.async pipeline, ONE __syncthreads per chunk:
//   CP_WAIT(stage ch ready) -> sync -> prefetch stage (ch+2)%3 -> compute.
// (prefetch-after-sync is race-free: that buffer was last read at iter ch-1,
//  and every warp passed that compute before this barrier.)
// SMEM: per tile 128 rows x 128B; row = [hi k0..31 | lo k0..31], chunk
// swizzle c' = c ^ (row&7). Stage = 32KB; 3 stages = 96KB -> 2 CTA/SM.
// SPLIT=true: write bf16 hi/lo (Chi/Clo) instead of fp32 C.
// ---------------------------------------------------------------------------
template<bool BIAS, bool SPLIT>
__global__ __launch_bounds__(256, 2)
void gemm_mma(const __nv_bfloat16* __restrict__ Ahi, const __nv_bfloat16* __restrict__ Alo,
              const __nv_bfloat16* __restrict__ Bhi, const __nv_bfloat16* __restrict__ Blo,
              const float* __restrict__ bias, float* __restrict__ C,
              __nv_bfloat16* __restrict__ Chi, __nv_bfloat16* __restrict__ Clo,
              int M, int N, int K)
{
    extern __shared__ char smem[];
    const uint32_t sbase = smem_u32(smem);
    const int STAGE = 32768, TILE = 16384;

    const int tid  = threadIdx.x;
    const int warp = tid >> 5;
    const int lane = tid & 31;
    const int bm = blockIdx.y << 7;
    const int bn = blockIdx.x << 7;

    const int wm = (warp & 3) * 32;
    const int wn = (warp >> 2) * 64;

    const int aRow = (lane & 7) + ((lane & 8) ? 8 : 0);
    const int aCh  = (lane & 16) ? 1 : 0;
    const int bRow = (lane & 7) + ((lane & 16) ? 8 : 0);
    const int bCh  = (lane & 8) ? 1 : 0;

    float acc[2][8][4];
#pragma unroll
    for (int mi = 0; mi < 2; mi++)
#pragma unroll
        for (int nj = 0; nj < 8; nj++)
#pragma unroll
            for (int e = 0; e < 4; e++) acc[mi][nj][e] = 0.f;

    const int nk = K >> 5;

    // stage loader: 2048 16B-chunks (A 1024 + B 1024), 8 per thread
    auto load_stage = [&](int s, int k0) {
        uint32_t sa = sbase + s * STAGE;
#pragma unroll
        for (int i = 0; i < 8; i++) {
            int idx  = tid + i * 256;
            int tile = idx >> 10;                 // 0 = A, 1 = B
            int row  = (idx >> 3) & 127;
            int c    = idx & 7;                   // 0-3 hi, 4-7 lo
            const __nv_bfloat16* src =
                (tile == 0) ? ((c < 4) ? Ahi : Alo) : ((c < 4) ? Bhi : Blo);
            int rowg = ((tile == 0) ? bm : bn) + row;
            int kk   = k0 + (c & 3) * 8;
            uint32_t dst = sa + (uint32_t)(tile * TILE + row * 128
                                           + ((c ^ (row & 7)) * 16));
            cp16(dst, src + (size_t)rowg * K + kk);
        }
        CP_COMMIT();
    };

    // prologue: two stages in flight
    load_stage(0, 0);
    load_stage(1, 32);

    int st = 0;  // stage index of current chunk
    for (int ch = 0; ch < nk; ch++) {
        const uint32_t sa = sbase + st * STAGE;
        if (ch + 1 < nk) CP_WAIT(1); else CP_WAIT(0);
        __syncthreads();
        // prefetch two chunks ahead into the stage read at iter ch-1
        if (ch + 2 < nk) {
            int ps = st + 2; if (ps >= 3) ps -= 3;
            load_stage(ps, (ch + 2) << 5);
        }

#pragma unroll
        for (int ks = 0; ks < 2; ks++) {
            uint32_t Ah[2][4], Al[2][4], Bh[8][2], Bl[8][2];
#pragma unroll
            for (int mi = 0; mi < 2; mi++) {
                int row  = wm + mi * 16 + aRow;
                int cHi  = (2 * ks + aCh) ^ (row & 7);
                int cLo  = (4 + 2 * ks + aCh) ^ (row & 7);
                ldsm4(Ah[mi], sa + (uint32_t)(row * 128 + cHi * 16));
                ldsm4(Al[mi], sa + (uint32_t)(row * 128 + cLo * 16));
            }
#pragma unroll
            for (int p = 0; p < 4; p++) {
                int row  = wn + p * 16 + bRow;
                int cHi  = (2 * ks + bCh) ^ (row & 7);
                int cLo  = (4 + 2 * ks + bCh) ^ (row & 7);
                ldsm4(&Bh[p * 2][0], sa + (uint32_t)(TILE + row * 128 + cHi * 16));
                ldsm4(&Bl[p * 2][0], sa + (uint32_t)(TILE + row * 128 + cLo * 16));
            }
#pragma unroll
            for (int mi = 0; mi < 2; mi++)
#pragma unroll
                for (int nj = 0; nj < 8; nj++)
                    mma_bf16(acc[mi][nj], Ah[mi], Bh[nj]);
#pragma unroll
            for (int mi = 0; mi < 2; mi++)
#pragma unroll
                for (int nj = 0; nj < 8; nj++)
                    mma_bf16(acc[mi][nj], Ah[mi], Bl[nj]);
#pragma unroll
            for (int mi = 0; mi < 2; mi++)
#pragma unroll
                for (int nj = 0; nj < 8; nj++)
                    mma_bf16(acc[mi][nj], Al[mi], Bh[nj]);
        }
        if (++st == 3) st = 0;
    }

    const int orow = bm + wm + (lane >> 2);
    const int ocol = bn + wn + (lane & 3) * 2;
#pragma unroll
    for (int mi = 0; mi < 2; mi++) {
        const int rA = orow + mi * 16;
#pragma unroll
        for (int nj = 0; nj < 8; nj++) {
            const int c = ocol + nj * 8;
            if (SPLIT) {
                uint32_t h0, l0, h1, l1;
                packsplit(h0, l0, acc[mi][nj][0], acc[mi][nj][1]);
                packsplit(h1, l1, acc[mi][nj][2], acc[mi][nj][3]);
                *reinterpret_cast<uint32_t*>(Chi + (size_t)rA * N + c)       = h0;
                *reinterpret_cast<uint32_t*>(Clo + (size_t)rA * N + c)       = l0;
                *reinterpret_cast<uint32_t*>(Chi + (size_t)(rA + 8) * N + c) = h1;
                *reinterpret_cast<uint32_t*>(Clo + (size_t)(rA + 8) * N + c) = l1;
            } else {
                float b0 = 0.f, b1 = 0.f;
                if (BIAS) { b0 = bias[c]; b1 = bias[c + 1]; }
                float2 v0, v1;
                v0.x = acc[mi][nj][0] + b0; v0.y = acc[mi][nj][1] + b1;
                v1.x = acc[mi][nj][2] + b0; v1.y = acc[mi][nj][3] + b1;
                *reinterpret_cast<float2*>(&C[(size_t)rA * N + c])       = v0;
                *reinterpret_cast<float2*>(&C[(size_t)(rA + 8) * N + c]) = v1;
            }
        }
    }
}

// ---------------------------------------------------------------------------
// Tensorized flash attention (structure unchanged from round 9/10; capped at
// 128 regs via __launch_bounds__(256,2) so 2 CTAs co-reside: SMEM 110592 x 2
// = 221184B fits; warps/SM 8 -> 16).
// ---------------------------------------------------------------------------
__global__ __launch_bounds__(256, 2)
void attn_mma(const __nv_bfloat16* __restrict__ qhi, const __nv_bfloat16* __restrict__ qlo,
              const float* __restrict__ atts,
              __nv_bfloat16* __restrict__ ohi, __nv_bfloat16* __restrict__ olo)
{
    extern __shared__ char smem[];
    const uint32_t sb = smem_u32(smem);
    const int SOFF = 36864, SSTAGE = 36864, TILE = 9216;

    const int tid = threadIdx.x, warp = tid >> 5, lane = tid & 31;
    const int qt = blockIdx.x, h = blockIdx.y, b = blockIdx.z;
    const int N = 1024, C3 = 3072;
    const float scale = 0.125f;

    const int aRow = (lane & 7) + ((lane & 8) ? 8 : 0);
    const int aKb  = (lane & 16) ? 16 : 0;
    const int bRow = (lane & 7) + ((lane & 16) ? 8 : 0);
    const int bKb  = (lane & 8) ? 16 : 0;

    // ---- load Q tiles (hi, lo) ----
    {
        size_t base = (size_t)(b * 1024 + qt * 128) * C3 + h * 64;
#pragma unroll
        for (int i = 0; i < 8; i++) {
            int idx = tid + i * 256;
            const __nv_bfloat16* src = (idx < 1024) ? qhi : qlo;
            int r = (idx >> 3) & 127, c = idx & 7;
            cp16(sb + (uint32_t)(idx >> 10) * 18432 + r * 144 + c * 16,
                 src + base + (size_t)r * C3 + c * 8);
        }
        CP_COMMIT();
    }

    auto load_stage = [&](int s, int ck) {
        size_t base = (size_t)(b * 1024 + ck * 64) * C3 + h * 64;
#pragma unroll
        for (int i = 0; i < 8; i++) {
            int idx = tid + i * 256;
            int t = idx >> 9, r = (idx >> 3) & 63, c = idx & 7;
            const __nv_bfloat16* src = (t & 1) ? qlo : qhi;
            size_t off = base + (size_t)r * C3 + c * 8 + ((t < 2) ? 1024 : 2048);
            cp16(sb + SOFF + s * SSTAGE + t * TILE + r * 144 + c * 16, src + off);
        }
        CP_COMMIT();
    };
    load_stage(0, 0);

    uint32_t Qh[4][4], Ql[4][4];
    float o[8][4];
#pragma unroll
    for (int nb = 0; nb < 8; nb++)
#pragma unroll
        for (int e = 0; e < 4; e++) o[nb][e] = 0.f;
    float m0 = -1e30f, m1 = -1e30f, l0 = 0.f, l1 = 0.f;

    const float* attsr0 = atts + (size_t)b * N * N
                        + (size_t)(qt * 128 + warp * 16 + (lane >> 2)) * N;
    const float* attsr8 = attsr0 + 8 * N;

    for (int ck = 0; ck < 16; ck++) {
        if (ck < 15) { load_stage((ck + 1) & 1, ck + 1); CP_WAIT(1); }
        else         { CP_WAIT(0); }
        __syncthreads();

        if (ck == 0) {
#pragma unroll
            for (int ks = 0; ks < 4; ks++) {
                uint32_t qa = sb + (uint32_t)((warp * 16 + aRow) * 144 + ks * 32 + aKb);
                ldsm4(Qh[ks], qa);
                ldsm4(Ql[ks], qa + 18432);
            }
        }

        const uint32_t kb_ = sb + SOFF + (uint32_t)(ck & 1) * SSTAGE;

        // ---- S = Q K^T (3-term) ----
        float s[8][4];
#pragma unroll
        for (int nb = 0; nb < 8; nb++)
#pragma unroll
            for (int e = 0; e < 4; e++) s[nb][e] = 0.f;

#pragma unroll
        for (int ks = 0; ks < 4; ks++) {
            uint32_t Kh[8][2], Kl[8][2];
#pragma unroll
            for (int p = 0; p < 4; p++) {
                uint32_t ka = kb_ + (uint32_t)((p * 16 + bRow) * 144 + ks * 32 + bKb);
                ldsm4(&Kh[p * 2][0], ka);
                ldsm4(&Kl[p * 2][0], ka + TILE);
            }
#pragma unroll
            for (int nb = 0; nb < 8; nb++) mma_bf16(s[nb], Qh[ks], Kh[nb]);
#pragma unroll
            for (int nb = 0; nb < 8; nb++) mma_bf16(s[nb], Qh[ks], Kl[nb]);
#pragma unroll
            for (int nb = 0; nb < 8; nb++) mma_bf16(s[nb], Ql[ks], Kh[nb]);
        }

        // ---- scale + mask ----
#pragma unroll
        for (int nb = 0; nb < 8; nb++) {
            int cb = ck * 64 + nb * 8 + (lane & 3) * 2;
            float2 ma = *reinterpret_cast<const float2*>(attsr0 + cb);
            float2 mb = *reinterpret_cast<const float2*>(attsr8 + cb);
            s[nb][0] = fmaf(s[nb][0], scale, ma.x);
            s[nb][1] = fmaf(s[nb][1], scale, ma.y);
            s[nb][2] = fmaf(s[nb][2], scale, mb.x);
            s[nb][3] = fmaf(s[nb][3], scale, mb.y);
        }

        // ---- online softmax ----
        float mx0 = -1e30f, mx1 = -1e30f;
#pragma unroll
        for (int nb = 0; nb < 8; nb++) {
            mx0 = fmaxf(mx0, fmaxf(s[nb][0], s[nb][1]));
            mx1 = fmaxf(mx1, fmaxf(s[nb][2], s[nb][3]));
        }
        mx0 = fmaxf(mx0, __shfl_xor_sync(0xffffffffu, mx0, 1, 32));
        mx0 = fmaxf(mx0, __shfl_xor_sync(0xffffffffu, mx0, 2, 32));
        mx1 = fmaxf(mx1, __shfl_xor_sync(0xffffffffu, mx1, 1, 32));
        mx1 = fmaxf(mx1, __shfl_xor_sync(0xffffffffu, mx1, 2, 32));
        float mn0 = fmaxf(m0, mx0), mn1 = fmaxf(m1, mx1);
        float al0 = __expf(m0 - mn0), al1 = __expf(m1 - mn1);
        m0 = mn0; m1 = mn1;

        float rs0 = 0.f, rs1 = 0.f;
#pragma unroll
        for (int nb = 0; nb < 8; nb++) {
            s[nb][0] = __expf(s[nb][0] - mn0);
            s[nb][1] = __expf(s[nb][1] - mn0);
            s[nb][2] = __expf(s[nb][2] - mn1);
            s[nb][3] = __expf(s[nb][3] - mn1);
            rs0 += s[nb][0] + s[nb][1];
            rs1 += s[nb][2] + s[nb][3];
        }
        rs0 += __shfl_xor_sync(0xffffffffu, rs0, 1, 32);
        rs0 += __shfl_xor_sync(0xffffffffu, rs0, 2, 32);
        rs1 += __shfl_xor_sync(0xffffffffu, rs1, 1, 32);
        rs1 += __shfl_xor_sync(0xffffffffu, rs1, 2, 32);
        l0 = l0 * al0 + rs0;
        l1 = l1 * al1 + rs1;

#pragma unroll
        for (int nb = 0; nb < 8; nb++) {
            o[nb][0] *= al0; o[nb][1] *= al0;
            o[nb][2] *= al1; o[nb][3] *= al1;
        }

        // ---- pack P -> A fragments (hi/lo) ----
        uint32_t Ph[4][4], Pl[4][4];
#pragma unroll
        for (int kb2 = 0; kb2 < 4; kb2++) {
            packsplit(Ph[kb2][0], Pl[kb2][0], s[2 * kb2][0],     s[2 * kb2][1]);
            packsplit(Ph[kb2][1], Pl[kb2][1], s[2 * kb2][2],     s[2 * kb2][3]);
            packsplit(Ph[kb2][2], Pl[kb2][2], s[2 * kb2 + 1][0], s[2 * kb2 + 1][1]);
            packsplit(Ph[kb2][3], Pl[kb2][3], s[2 * kb2 + 1][2], s[2 * kb2 + 1][3]);
        }

        // ---- O += P V (3-term; V via ldmatrix.trans) ----
        const uint32_t vb = kb_ + 2 * TILE;
#pragma unroll
        for (int kb2 = 0; kb2 < 4; kb2++) {
            uint32_t Vh[8][2], Vl[8][2];
#pragma unroll
            for (int p = 0; p < 4; p++) {
                uint32_t va = vb + (uint32_t)((kb2 * 16 + aRow) * 144 + p * 32 + aKb);
                ldsm4t(&Vh[p * 2][0], va);
                ldsm4t(&Vl[p * 2][0], va + TILE);
            }
#pragma unroll
            for (int nb = 0; nb < 8; nb++) mma_bf16(o[nb], Ph[kb2], Vh[nb]);
#pragma unroll
            for (int nb = 0; nb < 8; nb++) mma_bf16(o[nb], Ph[kb2], Vl[nb]);
#pragma unroll
            for (int nb = 0; nb < 8; nb++) mma_bf16(o[nb], Pl[kb2], Vh[nb]);
        }
        __syncthreads();
    }

    // ---- epilogue: normalize, split to bf16 hi/lo, store ----
    float i0 = 1.f / l0, i1 = 1.f / l1;
    size_t ro = (size_t)(b * 1024 + qt * 128 + warp * 16 + (lane >> 2)) * 1024 + h * 64;
#pragma unroll
    for (int nb = 0; nb < 8; nb++) {
        int col = nb * 8 + (lane & 3) * 2;
        uint32_t hh, ll;
        packsplit(hh, ll, o[nb][0] * i0, o[nb][1] * i0);
        *reinterpret_cast<uint32_t*>(ohi + ro + col) = hh;
        *reinterpret_cast<uint32_t*>(olo + ro + col) = ll;
        packsplit(hh, ll, o[nb][2] * i1, o[nb][3] * i1);
        *reinterpret_cast<uint32_t*>(ohi + ro + 8 * 1024 + col) = hh;
        *reinterpret_cast<uint32_t*>(olo + ro + 8 * 1024 + col) = ll;
    }
}

// ---------------------------------------------------------------------------
// Launch sequence
// inputs: 0 x, 1 text_embeds(unused), 2 image_atts, 3 qkv_w, 4 proj_w, 5 proj_b
// ---------------------------------------------------------------------------
extern "C" void kernel_launch(void* const* d_in, const int* in_sizes, int n_in,
                              void* d_out, int out_size)
{
    (void)in_sizes; (void)n_in; (void)out_size;
    const float* x      = (const float*)d_in[0];
    const float* atts   = (const float*)d_in[2];
    const float* qkv_w  = (const float*)d_in[3];
    const float* proj_w = (const float*)d_in[4];
    const float* proj_b = (const float*)d_in[5];
    float* out = (float*)d_out;

    __nv_bfloat16 *qkvhi, *qkvlo, *xhi, *xlo, *w1hi, *w1lo, *ahi, *alo, *w2hi, *w2lo;
    cudaGetSymbolAddress((void**)&qkvhi, g_qkvhi);
    cudaGetSymbolAddress((void**)&qkvlo, g_qkvlo);
    cudaGetSymbolAddress((void**)&xhi,  g_xhi);
    cudaGetSymbolAddress((void**)&xlo,  g_xlo);
    cudaGetSymbolAddress((void**)&w1hi, g_w1hi);
    cudaGetSymbolAddress((void**)&w1lo, g_w1lo);
    cudaGetSymbolAddress((void**)&ahi,  g_ahi);
    cudaGetSymbolAddress((void**)&alo,  g_alo);
    cudaGetSymbolAddress((void**)&w2hi, g_w2hi);
    cudaGetSymbolAddress((void**)&w2lo, g_w2lo);

    cudaFuncSetAttribute(gemm_mma<false, true>, cudaFuncAttributeMaxDynamicSharedMemorySize, 98304);
    cudaFuncSetAttribute(gemm_mma<true, false>, cudaFuncAttributeMaxDynamicSharedMemorySize, 98304);
    cudaFuncSetAttribute(attn_mma, cudaFuncAttributeMaxDynamicSharedMemorySize, 110592);

    // 1) split x; transpose+split weights
    split_kernel<<<8192, 256>>>(x, xhi, xlo, 8192 * 1024 / 4);
    tsplit_kernel<<<dim3(96, 32), dim3(32, 8)>>>(qkv_w, w1hi, w1lo, 1024, 3072);
    tsplit_kernel<<<dim3(32, 32), dim3(32, 8)>>>(proj_w, w2hi, w2lo, 1024, 1024);

    // 2) qkv = x @ qkv_w  (HMMA 3-term, bf16 hi/lo output)
    gemm_mma<false, true><<<dim3(24, 64), 256, 98304>>>(
        xhi, xlo, w1hi, w1lo, nullptr, nullptr, qkvhi, qkvlo, 8192, 3072, 1024);

    // 3) tensorized flash attention (bf16 hi/lo in and out)
    attn_mma<<<dim3(8, 16, 8), 256, 110592>>>(qkvhi, qkvlo, atts, ahi, alo);

    // 4) out = attn @ proj_w + bias  (HMMA 3-term, fp32 output)
    gemm_mma<true, false><<<dim3(8, 64), 256, 98304>>>(
        ahi, alo, w2hi, w2lo, proj_b, out, nullptr, nullptr, 8192, 1024, 1024);
}